// round 9
// baseline (speedup 1.0000x reference)
#include <cuda_runtime.h>
#include <cstdint>

// ---------------------------------------------------------------------------
// NonLocalMSA fp32, round 8: R7 (cp.async double-buffered K2/K4, channel-split
// K1) with K2/K4 buffers moved to DYNAMIC shared memory (static smem is capped
// at 48KB -> R7 ptxas failure).
// ---------------------------------------------------------------------------

#define HW 65536  // 256*256

__device__ float g_qkv[16ull * 192 * 256 * 256];  // 805 MB
__device__ float g_av [16ull *  64 * 256 * 256];  // 268 MB
__device__ float g_sim[1024ull * 64 * 64];        // 16 MB (8 partials per (b,h))
__device__ float g_attn[128ull * 64 * 64];        // 2 MB

__device__ __forceinline__ void cp_async4(uint32_t saddr, const float* gptr) {
    asm volatile("cp.async.ca.shared.global [%0], [%1], 4;" :: "r"(saddr), "l"(gptr));
}
__device__ __forceinline__ void cp_commit() {
    asm volatile("cp.async.commit_group;");
}
__device__ __forceinline__ void cp_wait0() {
    asm volatile("cp.async.wait_group 0;" ::: "memory");
}

#define TBUF (64 * 68)          // one tile buffer, floats
#define TBUFB (TBUF * 4)        // bytes

// ===========================================================================
// K1: fused 1x1 qkv + 3x3 depthwise. 16x16 tile (halo 18x18), channels split
// into two 32-ch halves so smem fits 2 blocks/SM.
// ===========================================================================
#define HPAD 328   // 18*18=324 padded to 328 (82 float4)
#define OC 48

extern __shared__ float dsm[];

__global__ __launch_bounds__(512, 2) void k1_qkv_dw(
    const float* __restrict__ x, const float* __restrict__ wqkv,
    const float* __restrict__ wdw)
{
    float* sx  = dsm;                 // [32][HPAD]
    float* sq  = sx + 32 * HPAD;      // [OC][HPAD]
    float* sw  = sq + OC * HPAD;      // [32 c][OC]
    float* sdw = sw + 32 * OC;        // [OC][9]

    const int b = blockIdx.z, ty = blockIdx.y, tx = blockIdx.x;
    const int tid = threadIdx.x;
    const float* xb = x + (size_t)b * 64 * HW;

    const float4* sx4 = (const float4*)sx;
    const float4* sw4 = (const float4*)sw;

    const int og = (tid < 486) ? tid / 81 : 0;
    const int pg = (tid < 486) ? tid - og * 81 : 0;

    for (int ocb = 0; ocb < 4; ocb++) {
        const int o0 = ocb * OC;
        float a0x=0,a0y=0,a0z=0,a0w=0, a1x=0,a1y=0,a1z=0,a1w=0;
        float a2x=0,a2y=0,a2z=0,a2w=0, a3x=0,a3y=0,a3z=0,a3w=0;
        float a4x=0,a4y=0,a4z=0,a4w=0, a5x=0,a5y=0,a5z=0,a5w=0;
        float a6x=0,a6y=0,a6z=0,a6w=0, a7x=0,a7y=0,a7z=0,a7w=0;

        for (int ch = 0; ch < 2; ch++) {
            __syncthreads();  // prior readers of sx/sw (and dw readers of sq) done
            // x half-tile with 1-halo, zero padded (no bias -> qkv(0)=0 -> exact)
            for (int idx = tid; idx < 32 * 324; idx += 512) {
                int c = idx / 324, p = idx - c * 324;
                int iy = p / 18, ix = p - iy * 18;
                int gy = ty * 16 - 1 + iy, gx = tx * 16 - 1 + ix;
                float v = 0.f;
                if ((unsigned)gy < 256u && (unsigned)gx < 256u)
                    v = xb[(ch * 32 + c) * HW + gy * 256 + gx];
                sx[c * HPAD + p] = v;
            }
            for (int idx = tid; idx < OC * 32; idx += 512) {
                int o = idx >> 5, c = idx & 31;          // coalesced in c
                sw[c * OC + o] = wqkv[(o0 + o) * 64 + ch * 32 + c];
            }
            if (ch == 0)
                for (int idx = tid; idx < OC * 9; idx += 512)
                    sdw[idx] = wdw[(o0 + idx / 9) * 9 + idx % 9];
            __syncthreads();

            if (tid < 486) {
                #pragma unroll 8
                for (int c = 0; c < 32; c++) {
                    float4 w0 = sw4[c * 12 + og * 2];
                    float4 w1 = sw4[c * 12 + og * 2 + 1];
                    float4 xv = sx4[c * 82 + pg];
                    a0x += w0.x*xv.x; a0y += w0.x*xv.y; a0z += w0.x*xv.z; a0w += w0.x*xv.w;
                    a1x += w0.y*xv.x; a1y += w0.y*xv.y; a1z += w0.y*xv.z; a1w += w0.y*xv.w;
                    a2x += w0.z*xv.x; a2y += w0.z*xv.y; a2z += w0.z*xv.z; a2w += w0.z*xv.w;
                    a3x += w0.w*xv.x; a3y += w0.w*xv.y; a3z += w0.w*xv.z; a3w += w0.w*xv.w;
                    a4x += w1.x*xv.x; a4y += w1.x*xv.y; a4z += w1.x*xv.z; a4w += w1.x*xv.w;
                    a5x += w1.y*xv.x; a5y += w1.y*xv.y; a5z += w1.y*xv.z; a5w += w1.y*xv.w;
                    a6x += w1.z*xv.x; a6y += w1.z*xv.y; a6z += w1.z*xv.z; a6w += w1.z*xv.w;
                    a7x += w1.w*xv.x; a7y += w1.w*xv.y; a7z += w1.w*xv.z; a7w += w1.w*xv.w;
                }
            }
        }
        if (tid < 486) {
            int ob = og * 8, pb = pg * 4;
            *(float4*)&sq[(ob+0) * HPAD + pb] = make_float4(a0x,a0y,a0z,a0w);
            *(float4*)&sq[(ob+1) * HPAD + pb] = make_float4(a1x,a1y,a1z,a1w);
            *(float4*)&sq[(ob+2) * HPAD + pb] = make_float4(a2x,a2y,a2z,a2w);
            *(float4*)&sq[(ob+3) * HPAD + pb] = make_float4(a3x,a3y,a3z,a3w);
            *(float4*)&sq[(ob+4) * HPAD + pb] = make_float4(a4x,a4y,a4z,a4w);
            *(float4*)&sq[(ob+5) * HPAD + pb] = make_float4(a5x,a5y,a5z,a5w);
            *(float4*)&sq[(ob+6) * HPAD + pb] = make_float4(a6x,a6y,a6z,a6w);
            *(float4*)&sq[(ob+7) * HPAD + pb] = make_float4(a7x,a7y,a7z,a7w);
        }
        __syncthreads();

        // depthwise 3x3 on interior; write to g_qkv
        for (int idx = tid; idx < OC * 256; idx += 512) {
            int o = idx >> 8, p = idx & 255;
            int iy = p >> 4, ix = p & 15;
            const float* q = &sq[o * HPAD + iy * 18 + ix];
            const float* d = &sdw[o * 9];
            float acc = d[0]*q[0]  + d[1]*q[1]  + d[2]*q[2]
                      + d[3]*q[18] + d[4]*q[19] + d[5]*q[20]
                      + d[6]*q[36] + d[7]*q[37] + d[8]*q[38];
            int gy = ty * 16 + iy, gx = tx * 16 + ix;
            g_qkv[(((size_t)b * 192 + o0 + o) * 256 + gy) * 256 + gx] = acc;
        }
    }
}

// ===========================================================================
// K2: sim partials. Block=(b,h,r,half): C[64,64] += A[64,1024]*B^T.
// cp.async double-buffered (dynamic smem: As[2] | Bs[2], 69,632 B).
// ===========================================================================
__global__ __launch_bounds__(256) void k2_sim()
{
    float* As0 = dsm;               // As[2][64*68]
    float* Bs0 = dsm + 2 * TBUF;    // Bs[2][64*68]
    const int blk = blockIdx.x;
    const int half = blk & 1, r = (blk >> 1) & 3, h = (blk >> 3) & 7, b = blk >> 6;
    const int tid = threadIdx.x, ti = tid >> 4, tj = tid & 15;
    const int yoff = h * 4 + r;

    const float* qbase = g_qkv + (size_t)b * 192 * HW;
    const float* kbase = qbase + (size_t)64 * HW;

    int soff[16];  // byte offset within one buffer
    int goff[16];  // gmem float offset within a 2-channel chunk
    #pragma unroll
    for (int p = 0; p < 16; p++) {
        int idx = tid + p * 256;
        int t = idx >> 6, kl = idx & 63;
        int chp = kl >> 5, col = kl & 31;
        soff[p] = (kl * 68 + t) * 4;
        goff[p] = chp * HW + ((t >> 3) * 32 + yoff) * 256 + (t & 7) * 32 + col;
    }

    const uint32_t As_b = (uint32_t)__cvta_generic_to_shared(As0);
    const uint32_t Bs_b = (uint32_t)__cvta_generic_to_shared(Bs0);

    const int kc0 = half * 16;
    {   // prologue: chunk kc0 -> buffer 0
        const float* qc = qbase + (size_t)kc0 * 2 * HW;
        const float* kp = kbase + (size_t)kc0 * 2 * HW;
        #pragma unroll
        for (int p = 0; p < 16; p++) {
            cp_async4(As_b + soff[p], qc + goff[p]);
            cp_async4(Bs_b + soff[p], kp + goff[p]);
        }
        cp_commit();
    }

    float c00=0,c01=0,c02=0,c03=0, c10=0,c11=0,c12=0,c13=0;
    float c20=0,c21=0,c22=0,c23=0, c30=0,c31=0,c32=0,c33=0;

    for (int kc = kc0; kc < kc0 + 16; kc++) {
        const int cur = (kc - kc0) & 1;
        cp_wait0();
        __syncthreads();  // cur data visible to all; prev compute done -> nxt free
        if (kc + 1 < kc0 + 16) {
            const int nxt = cur ^ 1;
            const float* qc = qbase + (size_t)(kc + 1) * 2 * HW;
            const float* kp = kbase + (size_t)(kc + 1) * 2 * HW;
            #pragma unroll
            for (int p = 0; p < 16; p++) {
                cp_async4(As_b + nxt * TBUFB + soff[p], qc + goff[p]);
                cp_async4(Bs_b + nxt * TBUFB + soff[p], kp + goff[p]);
            }
            cp_commit();
        }
        const float4* A4 = (const float4*)(As0 + cur * TBUF);
        const float4* B4 = (const float4*)(Bs0 + cur * TBUF);
        #pragma unroll 8
        for (int kk = 0; kk < 64; kk++) {
            float4 av = A4[kk * 17 + ti];
            float4 bv = B4[kk * 17 + tj];
            c00 += av.x*bv.x; c01 += av.x*bv.y; c02 += av.x*bv.z; c03 += av.x*bv.w;
            c10 += av.y*bv.x; c11 += av.y*bv.y; c12 += av.y*bv.z; c13 += av.y*bv.w;
            c20 += av.z*bv.x; c21 += av.z*bv.y; c22 += av.z*bv.z; c23 += av.z*bv.w;
            c30 += av.w*bv.x; c31 += av.w*bv.y; c32 += av.w*bv.z; c33 += av.w*bv.w;
        }
    }
    float* so = g_sim + (size_t)blk * 4096;
    *(float4*)&so[(ti*4+0)*64 + tj*4] = make_float4(c00,c01,c02,c03);
    *(float4*)&so[(ti*4+1)*64 + tj*4] = make_float4(c10,c11,c12,c13);
    *(float4*)&so[(ti*4+2)*64 + tj*4] = make_float4(c20,c21,c22,c23);
    *(float4*)&so[(ti*4+3)*64 + tj*4] = make_float4(c30,c31,c32,c33);
}

// ===========================================================================
// K3: softmax over j(64) of scale * (sum of 8 partials) + pos_emb
// ===========================================================================
__global__ __launch_bounds__(128) void k3_softmax(const float* __restrict__ pos)
{
    const float SCALE = 0.011048543456039806f;  // 8192^-0.5
    int row = blockIdx.x * 4 + (threadIdx.x >> 5);
    int lane = threadIdx.x & 31;
    int bh = row >> 6, i = row & 63;
    const float* s0 = g_sim + (size_t)bh * 8 * 4096 + i * 64;
    const float* pe = pos + (bh & 7) * 4096 + i * 64;
    float acc1 = 0.f, acc2 = 0.f;
    #pragma unroll
    for (int p = 0; p < 8; p++) {
        acc1 += s0[p * 4096 + lane];
        acc2 += s0[p * 4096 + lane + 32];
    }
    float v1 = SCALE * acc1 + pe[lane];
    float v2 = SCALE * acc2 + pe[lane + 32];
    float m = fmaxf(v1, v2);
    #pragma unroll
    for (int o = 16; o; o >>= 1) m = fmaxf(m, __shfl_xor_sync(0xffffffffu, m, o));
    float e1 = __expf(v1 - m), e2 = __expf(v2 - m);
    float s = e1 + e2;
    #pragma unroll
    for (int o = 16; o; o >>= 1) s += __shfl_xor_sync(0xffffffffu, s, o);
    float inv = 1.f / s;
    g_attn[(size_t)row * 64 + lane]      = e1 * inv;
    g_attn[(size_t)row * 64 + lane + 32] = e2 * inv;
}

// ===========================================================================
// K4: out = attn @ V. Block=(b,h,r,cg): 16 of 32 (2ch x 32col) chunks.
// cp.async double-buffered V loads (dynamic smem: At | Vs[2], 52,224 B).
// ===========================================================================
__global__ __launch_bounds__(256) void k4_av()
{
    float* At  = dsm;           // [64 j][68 t]
    float* Vs0 = dsm + TBUF;    // Vs[2][64*68]
    const int blk = blockIdx.x;
    const int cg = blk & 1, r = (blk >> 1) & 3, h = (blk >> 3) & 7, b = blk >> 6;
    const int tid = threadIdx.x, ti = tid >> 4, tj = tid & 15;
    const int yoff = h * 4 + r;

    const float* ap = g_attn + (size_t)(b * 8 + h) * 4096;
    for (int idx = tid; idx < 4096; idx += 256) {
        int t = idx >> 6, j = idx & 63;
        At[j * 68 + t] = ap[t * 64 + j];
    }
    const float* vbase = g_qkv + ((size_t)b * 192 + 128) * HW;
    float* ob = g_av + (size_t)b * 64 * HW;
    const float4* At4 = (const float4*)At;

    int soff[16];  // byte offset within one Vs buffer: row j, col kl
    int goff[16];
    #pragma unroll
    for (int p = 0; p < 16; p++) {
        int idx = tid + p * 256;
        int j = idx >> 6, kl = idx & 63;
        int chp = kl >> 5, col = kl & 31;
        soff[p] = (j * 68 + kl) * 4;
        goff[p] = chp * HW + ((j >> 3) * 32 + yoff) * 256 + (j & 7) * 32 + col;
    }

    const uint32_t Vs_b = (uint32_t)__cvta_generic_to_shared(Vs0);

    const int cp0 = cg * 16;
    {   // prologue: chunk cp0 -> buffer 0
        const float* vc = vbase + (size_t)cp0 * 2 * HW;
        #pragma unroll
        for (int p = 0; p < 16; p++)
            cp_async4(Vs_b + soff[p], vc + goff[p]);
        cp_commit();
    }

    for (int cp = cp0; cp < cp0 + 16; cp++) {
        const int cur = (cp - cp0) & 1;
        cp_wait0();
        __syncthreads();  // also publishes At on first iteration
        if (cp + 1 < cp0 + 16) {
            const int nxt = cur ^ 1;
            const float* vc = vbase + (size_t)(cp + 1) * 2 * HW;
            #pragma unroll
            for (int p = 0; p < 16; p++)
                cp_async4(Vs_b + nxt * TBUFB + soff[p], vc + goff[p]);
            cp_commit();
        }
        const float4* V4 = (const float4*)(Vs0 + cur * TBUF);
        float c00=0,c01=0,c02=0,c03=0, c10=0,c11=0,c12=0,c13=0;
        float c20=0,c21=0,c22=0,c23=0, c30=0,c31=0,c32=0,c33=0;
        #pragma unroll 8
        for (int kk = 0; kk < 64; kk++) {
            float4 av = At4[kk * 17 + ti];
            float4 vv = V4[kk * 17 + tj];
            c00 += av.x*vv.x; c01 += av.x*vv.y; c02 += av.x*vv.z; c03 += av.x*vv.w;
            c10 += av.y*vv.x; c11 += av.y*vv.y; c12 += av.y*vv.z; c13 += av.y*vv.w;
            c20 += av.z*vv.x; c21 += av.z*vv.y; c22 += av.z*vv.z; c23 += av.z*vv.w;
            c30 += av.w*vv.x; c31 += av.w*vv.y; c32 += av.w*vv.z; c33 += av.w*vv.w;
        }
        int cc0 = tj * 4, chp = cc0 >> 5, col0 = cc0 & 31;
        size_t cbase = (size_t)(cp * 2 + chp) * HW;
        float4 rows[4] = { make_float4(c00,c01,c02,c03), make_float4(c10,c11,c12,c13),
                           make_float4(c20,c21,c22,c23), make_float4(c30,c31,c32,c33) };
        #pragma unroll
        for (int ii = 0; ii < 4; ii++) {
            int t = ti * 4 + ii;
            int y = (t >> 3) * 32 + yoff;
            int xx = (t & 7) * 32 + col0;
            *(float4*)&ob[cbase + y * 256 + xx] = rows[ii];
        }
    }
}

// ===========================================================================
// K5: 1x1 projection + bias. Block = 128 positions; 8-out x 4-pos tiles.
// ===========================================================================
__global__ __launch_bounds__(256) void k5_proj(
    const float* __restrict__ wp, const float* __restrict__ bp,
    float* __restrict__ out)
{
    float* Ws = dsm;             // [64 c][68] (o contiguous)
    float* Xs = Ws + 64 * 68;    // [64 c][132] (p contiguous)
    const int blk = blockIdx.x;  // 8192 = 16 b * 256 y * 2 xh
    const int b = blk >> 9;
    const int rem = blk & 511;
    const int y = rem >> 1, x0 = (rem & 1) << 7;
    const int tid = threadIdx.x, to = tid >> 5, tp = tid & 31;

    const float* ib = g_av + (size_t)b * 64 * HW + y * 256 + x0;
    for (int idx = tid; idx < 4096; idx += 256) {
        int o = idx >> 6, c = idx & 63;          // coalesced read in c
        Ws[c * 68 + o] = wp[o * 64 + c];
    }
    #pragma unroll
    for (int p = 0; p < 32; p++) {
        int idx = tid + p * 256;
        int c = idx >> 7, px = idx & 127;
        Xs[c * 132 + px] = ib[(size_t)c * HW + px];
    }
    __syncthreads();

    const float4* Ws4 = (const float4*)Ws;
    const float4* Xs4 = (const float4*)Xs;
    float a0x=0,a0y=0,a0z=0,a0w=0, a1x=0,a1y=0,a1z=0,a1w=0;
    float a2x=0,a2y=0,a2z=0,a2w=0, a3x=0,a3y=0,a3z=0,a3w=0;
    float a4x=0,a4y=0,a4z=0,a4w=0, a5x=0,a5y=0,a5z=0,a5w=0;
    float a6x=0,a6y=0,a6z=0,a6w=0, a7x=0,a7y=0,a7z=0,a7w=0;
    #pragma unroll 8
    for (int c = 0; c < 64; c++) {
        float4 w0 = Ws4[c * 17 + to * 2];
        float4 w1 = Ws4[c * 17 + to * 2 + 1];
        float4 xv = Xs4[c * 33 + tp];
        a0x += w0.x*xv.x; a0y += w0.x*xv.y; a0z += w0.x*xv.z; a0w += w0.x*xv.w;
        a1x += w0.y*xv.x; a1y += w0.y*xv.y; a1z += w0.y*xv.z; a1w += w0.y*xv.w;
        a2x += w0.z*xv.x; a2y += w0.z*xv.y; a2z += w0.z*xv.z; a2w += w0.z*xv.w;
        a3x += w0.w*xv.x; a3y += w0.w*xv.y; a3z += w0.w*xv.z; a3w += w0.w*xv.w;
        a4x += w1.x*xv.x; a4y += w1.x*xv.y; a4z += w1.x*xv.z; a4w += w1.x*xv.w;
        a5x += w1.y*xv.x; a5y += w1.y*xv.y; a5z += w1.y*xv.z; a5w += w1.y*xv.w;
        a6x += w1.z*xv.x; a6y += w1.z*xv.y; a6z += w1.z*xv.z; a6w += w1.z*xv.w;
        a7x += w1.w*xv.x; a7y += w1.w*xv.y; a7z += w1.w*xv.z; a7w += w1.w*xv.w;
    }
    float* op = out + (size_t)b * 64 * HW + y * 256 + x0 + tp * 4;
    const int ob8 = to * 8;
    float4 res[8] = { make_float4(a0x,a0y,a0z,a0w), make_float4(a1x,a1y,a1z,a1w),
                      make_float4(a2x,a2y,a2z,a2w), make_float4(a3x,a3y,a3z,a3w),
                      make_float4(a4x,a4y,a4z,a4w), make_float4(a5x,a5y,a5z,a5w),
                      make_float4(a6x,a6y,a6z,a6w), make_float4(a7x,a7y,a7z,a7w) };
    #pragma unroll
    for (int rr = 0; rr < 8; rr++) {
        float bb = bp[ob8 + rr];
        float4 v = res[rr];
        v.x += bb; v.y += bb; v.z += bb; v.w += bb;
        *(float4*)&op[(size_t)(ob8 + rr) * HW] = v;
    }
}

// ===========================================================================
extern "C" void kernel_launch(void* const* d_in, const int* in_sizes, int n_in,
                              void* d_out, int out_size)
{
    const float* x     = (const float*)d_in[0];
    const float* wqkv  = (const float*)d_in[1];
    const float* wdw   = (const float*)d_in[2];
    const float* wproj = (const float*)d_in[3];
    const float* bproj = (const float*)d_in[4];
    const float* pos   = (const float*)d_in[5];
    float* out = (float*)d_out;

    const int smem1 = (32 * HPAD + OC * HPAD + 32 * OC + OC * 9) * 4;  // 112,832 B
    const int smem2 = 4 * TBUFB;                                       // 69,632 B
    const int smem4 = 3 * TBUFB;                                       // 52,224 B
    const int smem5 = (64 * 68 + 64 * 132) * 4;                        // 51,200 B
    cudaFuncSetAttribute(k1_qkv_dw, cudaFuncAttributeMaxDynamicSharedMemorySize, smem1);
    cudaFuncSetAttribute(k2_sim,    cudaFuncAttributeMaxDynamicSharedMemorySize, smem2);
    cudaFuncSetAttribute(k4_av,     cudaFuncAttributeMaxDynamicSharedMemorySize, smem4);
    cudaFuncSetAttribute(k5_proj,   cudaFuncAttributeMaxDynamicSharedMemorySize, smem5);

    k1_qkv_dw<<<dim3(16, 16, 16), 512, smem1>>>(x, wqkv, wdw);
    k2_sim<<<1024, 256, smem2>>>();
    k3_softmax<<<2048, 128>>>(pos);
    k4_av<<<1024, 256, smem4>>>();
    k5_proj<<<8192, 256, smem5>>>(wproj, bproj, out);
}

// round 10
// speedup vs baseline: 1.1674x; 1.1674x over previous
#include <cuda_runtime.h>
#include <cuda_bf16.h>
#include <cstdint>

// ---------------------------------------------------------------------------
// NonLocalMSA fp32, round 10: K1 1x1 via bf16-split tensor-core mma
// (xh*wh + xl*wh + xh*wl), K2/K4 reverted to measured-best R6 variants.
// ---------------------------------------------------------------------------

#define HW 65536  // 256*256

__device__ float g_qkv[16ull * 192 * 256 * 256];  // 805 MB
__device__ float g_av [16ull *  64 * 256 * 256];  // 268 MB
__device__ float g_sim[1024ull * 64 * 64];        // 16 MB (8 partials per (b,h))
__device__ float g_attn[128ull * 64 * 64];        // 2 MB

extern __shared__ float dsm[];

__device__ __forceinline__ void mma_bf16(float* c,
    uint32_t a0, uint32_t a1, uint32_t a2, uint32_t a3,
    uint32_t b0, uint32_t b1)
{
    asm volatile(
        "mma.sync.aligned.m16n8k16.row.col.f32.bf16.bf16.f32 "
        "{%0,%1,%2,%3}, {%4,%5,%6,%7}, {%8,%9}, {%0,%1,%2,%3};"
        : "+f"(c[0]), "+f"(c[1]), "+f"(c[2]), "+f"(c[3])
        : "r"(a0), "r"(a1), "r"(a2), "r"(a3), "r"(b0), "r"(b1));
}

// ===========================================================================
// K1: fused 1x1 qkv (bf16-split MMA) + 3x3 depthwise (scalar).
// 16x16 tile, halo 18x18 = 324 pos, padded to M=336. K=64 ch. N=48 per ocb.
// smem: Xh/Xl [336 pos][72 ch] bf16, sq [48][336] f32, Wh/Wl [48][72] bf16.
// ===========================================================================
#define OC 48
#define XS 72     // ch stride in Xs (36 words -> conflict-free fragments)
#define SQS 336

__global__ __launch_bounds__(512, 1) void k1_qkv_dw(
    const float* __restrict__ x, const float* __restrict__ wqkv,
    const float* __restrict__ wdw)
{
    __nv_bfloat16* Xh = (__nv_bfloat16*)dsm;          // [336][XS]
    __nv_bfloat16* Xl = Xh + 336 * XS;
    float* sq         = (float*)(Xl + 336 * XS);      // [OC][SQS]
    __nv_bfloat16* Wh = (__nv_bfloat16*)(sq + OC * SQS);  // [OC][XS]
    __nv_bfloat16* Wl = Wh + OC * XS;
    float* sdw        = (float*)(Wl + OC * XS);       // [OC][9]

    const int b = blockIdx.z, ty = blockIdx.y, tx = blockIdx.x;
    const int tid = threadIdx.x;
    const int warp = tid >> 5, lane = tid & 31;
    const int gid = lane >> 2, tig = lane & 3;
    const float* xb = x + (size_t)b * 64 * HW;

    // Load x tile (halo, zero-pad; no bias -> qkv(0)=0 -> exact), split hi/lo.
    for (int idx = tid; idx < 64 * 324; idx += 512) {
        int c = idx / 324, p = idx - c * 324;
        int iy = p / 18, ix = p - iy * 18;
        int gy = ty * 16 - 1 + iy, gx = tx * 16 - 1 + ix;
        float v = 0.f;
        if ((unsigned)gy < 256u && (unsigned)gx < 256u)
            v = xb[c * HW + gy * 256 + gx];
        __nv_bfloat16 h = __float2bfloat16(v);
        Xh[p * XS + c] = h;
        Xl[p * XS + c] = __float2bfloat16(v - __bfloat162float(h));
    }
    // Zero pad rows 324..335 (ch 0..63 are the only cols fragments read).
    for (int idx = tid; idx < 12 * 64; idx += 512) {
        int p = 324 + (idx >> 6), c = idx & 63;
        Xh[p * XS + c] = __float2bfloat16(0.f);
        Xl[p * XS + c] = __float2bfloat16(0.f);
    }

    const uint32_t* Xh2 = (const uint32_t*)Xh;
    const uint32_t* Xl2 = (const uint32_t*)Xl;
    const uint32_t* Wh2 = (const uint32_t*)Wh;
    const uint32_t* Wl2 = (const uint32_t*)Wl;

    for (int ocb = 0; ocb < 4; ocb++) {
        const int o0 = ocb * OC;
        __syncthreads();  // Xs ready (1st); prev mma done w/ Ws, prev dw done w/ sq
        for (int idx = tid; idx < OC * 64; idx += 512) {
            int o = idx >> 6, c = idx & 63;
            float v = wqkv[(o0 + o) * 64 + c];
            __nv_bfloat16 h = __float2bfloat16(v);
            Wh[o * XS + c] = h;
            Wl[o * XS + c] = __float2bfloat16(v - __bfloat162float(h));
        }
        for (int idx = tid; idx < OC * 9; idx += 512)
            sdw[idx] = wdw[(o0 + idx / 9) * 9 + idx % 9];
        __syncthreads();

        // MMA: C[336 pos, 48 out] = X[336,64] * W^T. 21 m-tiles, 6 n-tiles.
        for (int mt = warp; mt < 21; mt += 16) {
            const int m0 = mt * 16;
            float acc[6][4];
            #pragma unroll
            for (int n = 0; n < 6; n++)
                acc[n][0] = acc[n][1] = acc[n][2] = acc[n][3] = 0.f;

            #pragma unroll
            for (int kb = 0; kb < 4; kb++) {
                const int kw = kb * 8;  // word offset = kb*16/2
                const int rA = (m0 + gid) * (XS / 2) + kw + tig;
                uint32_t ah0 = Xh2[rA];
                uint32_t ah1 = Xh2[rA + 8 * (XS / 2)];
                uint32_t ah2 = Xh2[rA + 4];
                uint32_t ah3 = Xh2[rA + 8 * (XS / 2) + 4];
                uint32_t al0 = Xl2[rA];
                uint32_t al1 = Xl2[rA + 8 * (XS / 2)];
                uint32_t al2 = Xl2[rA + 4];
                uint32_t al3 = Xl2[rA + 8 * (XS / 2) + 4];
                #pragma unroll
                for (int n = 0; n < 6; n++) {
                    const int rB = (n * 8 + gid) * (XS / 2) + kw + tig;
                    uint32_t bh0 = Wh2[rB], bh1 = Wh2[rB + 4];
                    uint32_t bl0 = Wl2[rB], bl1 = Wl2[rB + 4];
                    mma_bf16(acc[n], ah0, ah1, ah2, ah3, bh0, bh1);
                    mma_bf16(acc[n], al0, al1, al2, al3, bh0, bh1);
                    mma_bf16(acc[n], ah0, ah1, ah2, ah3, bl0, bl1);
                }
            }
            #pragma unroll
            for (int n = 0; n < 6; n++) {
                const int oo = n * 8 + 2 * tig;
                sq[oo * SQS + m0 + gid]           = acc[n][0];
                sq[(oo + 1) * SQS + m0 + gid]     = acc[n][1];
                sq[oo * SQS + m0 + gid + 8]       = acc[n][2];
                sq[(oo + 1) * SQS + m0 + gid + 8] = acc[n][3];
            }
        }
        __syncthreads();

        // depthwise 3x3 on interior; write to g_qkv
        for (int idx = tid; idx < OC * 256; idx += 512) {
            int o = idx >> 8, p = idx & 255;
            int iy = p >> 4, ix = p & 15;
            const float* q = &sq[o * SQS + iy * 18 + ix];
            const float* d = &sdw[o * 9];
            float acc = d[0]*q[0]  + d[1]*q[1]  + d[2]*q[2]
                      + d[3]*q[18] + d[4]*q[19] + d[5]*q[20]
                      + d[6]*q[36] + d[7]*q[37] + d[8]*q[38];
            int gy = ty * 16 + iy, gx = tx * 16 + ix;
            g_qkv[(((size_t)b * 192 + o0 + o) * 256 + gy) * 256 + gx] = acc;
        }
    }
}

// ===========================================================================
// K2: sim partials (R6 register-prefetch variant). Block=(b,h,r,half).
// ===========================================================================
__global__ __launch_bounds__(256) void k2_sim()
{
    __shared__ float As[64 * 68];  // [kl][t]
    __shared__ float Bs[64 * 68];
    const int blk = blockIdx.x;
    const int half = blk & 1, r = (blk >> 1) & 3, h = (blk >> 3) & 7, b = blk >> 6;
    const int tid = threadIdx.x, ti = tid >> 4, tj = tid & 15;
    const int yoff = h * 4 + r;

    const float* qbase = g_qkv + (size_t)b * 192 * HW;
    const float* kbase = qbase + (size_t)64 * HW;
    const float4* As4 = (const float4*)As;
    const float4* Bs4 = (const float4*)Bs;

    int tt[16], kk_[16];
    size_t goff[16];
    #pragma unroll
    for (int p = 0; p < 16; p++) {
        int idx = tid + p * 256;
        int t = idx >> 6, kl = idx & 63;
        int chp = kl >> 5, col = kl & 31;
        int y = (t >> 3) * 32 + yoff, xx = (t & 7) * 32 + col;
        tt[p] = t; kk_[p] = kl;
        goff[p] = (size_t)chp * HW + y * 256 + xx;
    }

    const int kc0 = half * 16;
    float pa[16], pb[16];
    #pragma unroll
    for (int p = 0; p < 16; p++) {
        size_t o = (size_t)kc0 * 2 * HW + goff[p];
        pa[p] = qbase[o]; pb[p] = kbase[o];
    }

    float c00=0,c01=0,c02=0,c03=0, c10=0,c11=0,c12=0,c13=0;
    float c20=0,c21=0,c22=0,c23=0, c30=0,c31=0,c32=0,c33=0;

    for (int kc = kc0; kc < kc0 + 16; kc++) {
        __syncthreads();
        #pragma unroll
        for (int p = 0; p < 16; p++) {
            As[kk_[p] * 68 + tt[p]] = pa[p];
            Bs[kk_[p] * 68 + tt[p]] = pb[p];
        }
        __syncthreads();
        if (kc + 1 < kc0 + 16) {
            #pragma unroll
            for (int p = 0; p < 16; p++) {
                size_t o = (size_t)(kc + 1) * 2 * HW + goff[p];
                pa[p] = qbase[o]; pb[p] = kbase[o];
            }
        }
        #pragma unroll 8
        for (int kk = 0; kk < 64; kk++) {
            float4 av = As4[kk * 17 + ti];
            float4 bv = Bs4[kk * 17 + tj];
            c00 += av.x*bv.x; c01 += av.x*bv.y; c02 += av.x*bv.z; c03 += av.x*bv.w;
            c10 += av.y*bv.x; c11 += av.y*bv.y; c12 += av.y*bv.z; c13 += av.y*bv.w;
            c20 += av.z*bv.x; c21 += av.z*bv.y; c22 += av.z*bv.z; c23 += av.z*bv.w;
            c30 += av.w*bv.x; c31 += av.w*bv.y; c32 += av.w*bv.z; c33 += av.w*bv.w;
        }
    }
    float* so = g_sim + (size_t)blk * 4096;
    *(float4*)&so[(ti*4+0)*64 + tj*4] = make_float4(c00,c01,c02,c03);
    *(float4*)&so[(ti*4+1)*64 + tj*4] = make_float4(c10,c11,c12,c13);
    *(float4*)&so[(ti*4+2)*64 + tj*4] = make_float4(c20,c21,c22,c23);
    *(float4*)&so[(ti*4+3)*64 + tj*4] = make_float4(c30,c31,c32,c33);
}

// ===========================================================================
// K3: softmax over j(64) of scale * (sum of 8 partials) + pos_emb
// ===========================================================================
__global__ __launch_bounds__(128) void k3_softmax(const float* __restrict__ pos)
{
    const float SCALE = 0.011048543456039806f;  // 8192^-0.5
    int row = blockIdx.x * 4 + (threadIdx.x >> 5);
    int lane = threadIdx.x & 31;
    int bh = row >> 6, i = row & 63;
    const float* s0 = g_sim + (size_t)bh * 8 * 4096 + i * 64;
    const float* pe = pos + (bh & 7) * 4096 + i * 64;
    float acc1 = 0.f, acc2 = 0.f;
    #pragma unroll
    for (int p = 0; p < 8; p++) {
        acc1 += s0[p * 4096 + lane];
        acc2 += s0[p * 4096 + lane + 32];
    }
    float v1 = SCALE * acc1 + pe[lane];
    float v2 = SCALE * acc2 + pe[lane + 32];
    float m = fmaxf(v1, v2);
    #pragma unroll
    for (int o = 16; o; o >>= 1) m = fmaxf(m, __shfl_xor_sync(0xffffffffu, m, o));
    float e1 = __expf(v1 - m), e2 = __expf(v2 - m);
    float s = e1 + e2;
    #pragma unroll
    for (int o = 16; o; o >>= 1) s += __shfl_xor_sync(0xffffffffu, s, o);
    float inv = 1.f / s;
    g_attn[(size_t)row * 64 + lane]      = e1 * inv;
    g_attn[(size_t)row * 64 + lane + 32] = e2 * inv;
}

// ===========================================================================
// K4: out = attn @ V (R6 register-prefetch variant). Block=(b,h,r,cg).
// ===========================================================================
__global__ __launch_bounds__(256) void k4_av()
{
    __shared__ float At[64 * 68];  // [j][t]
    __shared__ float Vs[64 * 68];  // [j][cc]
    const int blk = blockIdx.x;
    const int cg = blk & 1, r = (blk >> 1) & 3, h = (blk >> 3) & 7, b = blk >> 6;
    const int tid = threadIdx.x, ti = tid >> 4, tj = tid & 15;
    const int yoff = h * 4 + r;

    const float* ap = g_attn + (size_t)(b * 8 + h) * 4096;
    for (int idx = tid; idx < 4096; idx += 256) {
        int t = idx >> 6, j = idx & 63;
        At[j * 68 + t] = ap[t * 64 + j];
    }
    const float* vbase = g_qkv + ((size_t)b * 192 + 128) * HW;
    float* ob = g_av + (size_t)b * 64 * HW;
    const float4* At4 = (const float4*)At;
    const float4* Vs4 = (const float4*)Vs;

    int jj[16], kk_[16];
    size_t goff[16];
    #pragma unroll
    for (int p = 0; p < 16; p++) {
        int idx = tid + p * 256;
        int j = idx >> 6, kl = idx & 63;
        int chp = kl >> 5, col = kl & 31;
        int y = (j >> 3) * 32 + yoff, xx = (j & 7) * 32 + col;
        jj[p] = j; kk_[p] = kl;
        goff[p] = (size_t)chp * HW + y * 256 + xx;
    }

    const int cp0 = cg * 16;
    float pv[16];
    #pragma unroll
    for (int p = 0; p < 16; p++)
        pv[p] = vbase[(size_t)cp0 * 2 * HW + goff[p]];

    for (int cp = cp0; cp < cp0 + 16; cp++) {
        __syncthreads();
        #pragma unroll
        for (int p = 0; p < 16; p++)
            Vs[jj[p] * 68 + kk_[p]] = pv[p];
        __syncthreads();
        if (cp + 1 < cp0 + 16) {
            #pragma unroll
            for (int p = 0; p < 16; p++)
                pv[p] = vbase[(size_t)(cp + 1) * 2 * HW + goff[p]];
        }
        float c00=0,c01=0,c02=0,c03=0, c10=0,c11=0,c12=0,c13=0;
        float c20=0,c21=0,c22=0,c23=0, c30=0,c31=0,c32=0,c33=0;
        #pragma unroll 8
        for (int kk = 0; kk < 64; kk++) {
            float4 av = At4[kk * 17 + ti];
            float4 vv = Vs4[kk * 17 + tj];
            c00 += av.x*vv.x; c01 += av.x*vv.y; c02 += av.x*vv.z; c03 += av.x*vv.w;
            c10 += av.y*vv.x; c11 += av.y*vv.y; c12 += av.y*vv.z; c13 += av.y*vv.w;
            c20 += av.z*vv.x; c21 += av.z*vv.y; c22 += av.z*vv.z; c23 += av.z*vv.w;
            c30 += av.w*vv.x; c31 += av.w*vv.y; c32 += av.w*vv.z; c33 += av.w*vv.w;
        }
        int cc0 = tj * 4, chp = cc0 >> 5, col0 = cc0 & 31;
        size_t cbase = (size_t)(cp * 2 + chp) * HW;
        float4 rows[4] = { make_float4(c00,c01,c02,c03), make_float4(c10,c11,c12,c13),
                           make_float4(c20,c21,c22,c23), make_float4(c30,c31,c32,c33) };
        #pragma unroll
        for (int ii = 0; ii < 4; ii++) {
            int t = ti * 4 + ii;
            int y = (t >> 3) * 32 + yoff;
            int xx = (t & 7) * 32 + col0;
            *(float4*)&ob[cbase + y * 256 + xx] = rows[ii];
        }
    }
}

// ===========================================================================
// K5: 1x1 projection + bias. Block = 128 positions; 8-out x 4-pos tiles.
// ===========================================================================
__global__ __launch_bounds__(256) void k5_proj(
    const float* __restrict__ wp, const float* __restrict__ bp,
    float* __restrict__ out)
{
    float* Ws = dsm;             // [64 c][68]
    float* Xs = Ws + 64 * 68;    // [64 c][132]
    const int blk = blockIdx.x;  // 8192 = 16 b * 256 y * 2 xh
    const int b = blk >> 9;
    const int rem = blk & 511;
    const int y = rem >> 1, x0 = (rem & 1) << 7;
    const int tid = threadIdx.x, to = tid >> 5, tp = tid & 31;

    const float* ib = g_av + (size_t)b * 64 * HW + y * 256 + x0;
    for (int idx = tid; idx < 4096; idx += 256) {
        int o = idx >> 6, c = idx & 63;
        Ws[c * 68 + o] = wp[o * 64 + c];
    }
    #pragma unroll
    for (int p = 0; p < 32; p++) {
        int idx = tid + p * 256;
        int c = idx >> 7, px = idx & 127;
        Xs[c * 132 + px] = ib[(size_t)c * HW + px];
    }
    __syncthreads();

    const float4* Ws4 = (const float4*)Ws;
    const float4* Xs4 = (const float4*)Xs;
    float a0x=0,a0y=0,a0z=0,a0w=0, a1x=0,a1y=0,a1z=0,a1w=0;
    float a2x=0,a2y=0,a2z=0,a2w=0, a3x=0,a3y=0,a3z=0,a3w=0;
    float a4x=0,a4y=0,a4z=0,a4w=0, a5x=0,a5y=0,a5z=0,a5w=0;
    float a6x=0,a6y=0,a6z=0,a6w=0, a7x=0,a7y=0,a7z=0,a7w=0;
    #pragma unroll 8
    for (int c = 0; c < 64; c++) {
        float4 w0 = Ws4[c * 17 + to * 2];
        float4 w1 = Ws4[c * 17 + to * 2 + 1];
        float4 xv = Xs4[c * 33 + tp];
        a0x += w0.x*xv.x; a0y += w0.x*xv.y; a0z += w0.x*xv.z; a0w += w0.x*xv.w;
        a1x += w0.y*xv.x; a1y += w0.y*xv.y; a1z += w0.y*xv.z; a1w += w0.y*xv.w;
        a2x += w0.z*xv.x; a2y += w0.z*xv.y; a2z += w0.z*xv.z; a2w += w0.z*xv.w;
        a3x += w0.w*xv.x; a3y += w0.w*xv.y; a3z += w0.w*xv.z; a3w += w0.w*xv.w;
        a4x += w1.x*xv.x; a4y += w1.x*xv.y; a4z += w1.x*xv.z; a4w += w1.x*xv.w;
        a5x += w1.y*xv.x; a5y += w1.y*xv.y; a5z += w1.y*xv.z; a5w += w1.y*xv.w;
        a6x += w1.z*xv.x; a6y += w1.z*xv.y; a6z += w1.z*xv.z; a6w += w1.z*xv.w;
        a7x += w1.w*xv.x; a7y += w1.w*xv.y; a7z += w1.w*xv.z; a7w += w1.w*xv.w;
    }
    float* op = out + (size_t)b * 64 * HW + y * 256 + x0 + tp * 4;
    const int ob8 = to * 8;
    float4 res[8] = { make_float4(a0x,a0y,a0z,a0w), make_float4(a1x,a1y,a1z,a1w),
                      make_float4(a2x,a2y,a2z,a2w), make_float4(a3x,a3y,a3z,a3w),
                      make_float4(a4x,a4y,a4z,a4w), make_float4(a5x,a5y,a5z,a5w),
                      make_float4(a6x,a6y,a6z,a6w), make_float4(a7x,a7y,a7z,a7w) };
    #pragma unroll
    for (int rr = 0; rr < 8; rr++) {
        float bb = bp[ob8 + rr];
        float4 v = res[rr];
        v.x += bb; v.y += bb; v.z += bb; v.w += bb;
        *(float4*)&op[(size_t)(ob8 + rr) * HW] = v;
    }
}

// ===========================================================================
extern "C" void kernel_launch(void* const* d_in, const int* in_sizes, int n_in,
                              void* d_out, int out_size)
{
    const float* x     = (const float*)d_in[0];
    const float* wqkv  = (const float*)d_in[1];
    const float* wdw   = (const float*)d_in[2];
    const float* wproj = (const float*)d_in[3];
    const float* bproj = (const float*)d_in[4];
    const float* pos   = (const float*)d_in[5];
    float* out = (float*)d_out;

    const int smem1 = 2 * (336 * XS * 2) + OC * SQS * 4
                    + 2 * (OC * XS * 2) + OC * 9 * 4;   // 176,832 B
    const int smem5 = (64 * 68 + 64 * 132) * 4;          // 51,200 B
    cudaFuncSetAttribute(k1_qkv_dw, cudaFuncAttributeMaxDynamicSharedMemorySize, smem1);
    cudaFuncSetAttribute(k5_proj,   cudaFuncAttributeMaxDynamicSharedMemorySize, smem5);

    k1_qkv_dw<<<dim3(16, 16, 16), 512, smem1>>>(x, wqkv, wdw);
    k2_sim<<<1024, 256>>>();
    k3_softmax<<<2048, 128>>>(pos);
    k4_av<<<1024, 256>>>();
    k5_proj<<<8192, 256, smem5>>>(wproj, bproj, out);
}

// round 12
// speedup vs baseline: 1.2181x; 1.0434x over previous
#include <cuda_runtime.h>
#include <cuda_bf16.h>
#include <cstdint>

// ---------------------------------------------------------------------------
// NonLocalMSA fp32, round 12 (= round 11 resubmit; infra failure last round):
//  - K1 writes q,k as split bf16 planes (hi/lo), V as f32.
//  - K2 rewritten as bf16-split tensor-core MMA with cp.async double buffer.
//  - K1 mma warp-balance fix (42 units over 16 warps).
//  - 3 dummy launches appended to shift ncu capture onto k1.
// ---------------------------------------------------------------------------

#define HW 65536  // 256*256

__device__ __nv_bfloat16 g_qkh[16ull * 128 * 65536];  // 268 MB: q ch0-63, k ch64-127 (hi)
__device__ __nv_bfloat16 g_qkl[16ull * 128 * 65536];  // 268 MB: lo residual
__device__ float g_v  [16ull *  64 * 65536];          // 268 MB: V (f32)
__device__ float g_av [16ull *  64 * 65536];          // 268 MB
__device__ float g_sim[1024ull * 64 * 64];            // 16 MB (8 partials per (b,h))
__device__ float g_attn[128ull * 64 * 64];            // 2 MB
__device__ float g_dummy[32];

extern __shared__ float dsm[];

__device__ __forceinline__ void mma_bf16(float* c,
    uint32_t a0, uint32_t a1, uint32_t a2, uint32_t a3,
    uint32_t b0, uint32_t b1)
{
    asm volatile(
        "mma.sync.aligned.m16n8k16.row.col.f32.bf16.bf16.f32 "
        "{%0,%1,%2,%3}, {%4,%5,%6,%7}, {%8,%9}, {%0,%1,%2,%3};"
        : "+f"(c[0]), "+f"(c[1]), "+f"(c[2]), "+f"(c[3])
        : "r"(a0), "r"(a1), "r"(a2), "r"(a3), "r"(b0), "r"(b1));
}

__device__ __forceinline__ void cp16(uint32_t saddr, const void* gptr) {
    asm volatile("cp.async.cg.shared.global [%0], [%1], 16;" :: "r"(saddr), "l"(gptr));
}
__device__ __forceinline__ void cp_commit() {
    asm volatile("cp.async.commit_group;");
}
__device__ __forceinline__ void cp_wait0() {
    asm volatile("cp.async.wait_group 0;" ::: "memory");
}

// ===========================================================================
// K1: fused 1x1 qkv (bf16-split MMA) + 3x3 depthwise.
// 16x16 tile, halo 324 pos padded to 336. Writes q,k split planes, V f32.
// ===========================================================================
#define OC 48
#define XS 72     // ch stride in Xs (36 words -> conflict-free fragments)
#define SQS 336

__global__ __launch_bounds__(512, 1) void k1_qkv_dw(
    const float* __restrict__ x, const float* __restrict__ wqkv,
    const float* __restrict__ wdw)
{
    __nv_bfloat16* Xh = (__nv_bfloat16*)dsm;          // [336][XS]
    __nv_bfloat16* Xl = Xh + 336 * XS;
    float* sq         = (float*)(Xl + 336 * XS);      // [OC][SQS]
    __nv_bfloat16* Wh = (__nv_bfloat16*)(sq + OC * SQS);  // [OC][XS]
    __nv_bfloat16* Wl = Wh + OC * XS;
    float* sdw        = (float*)(Wl + OC * XS);       // [OC][9]

    const int b = blockIdx.z, ty = blockIdx.y, tx = blockIdx.x;
    const int tid = threadIdx.x;
    const int warp = tid >> 5, lane = tid & 31;
    const int gid = lane >> 2, tig = lane & 3;
    const float* xb = x + (size_t)b * 64 * HW;

    for (int idx = tid; idx < 64 * 324; idx += 512) {
        int c = idx / 324, p = idx - c * 324;
        int iy = p / 18, ix = p - iy * 18;
        int gy = ty * 16 - 1 + iy, gx = tx * 16 - 1 + ix;
        float v = 0.f;
        if ((unsigned)gy < 256u && (unsigned)gx < 256u)
            v = xb[c * HW + gy * 256 + gx];
        __nv_bfloat16 h = __float2bfloat16(v);
        Xh[p * XS + c] = h;
        Xl[p * XS + c] = __float2bfloat16(v - __bfloat162float(h));
    }
    for (int idx = tid; idx < 12 * 64; idx += 512) {
        int p = 324 + (idx >> 6), c = idx & 63;
        Xh[p * XS + c] = __float2bfloat16(0.f);
        Xl[p * XS + c] = __float2bfloat16(0.f);
    }

    const uint32_t* Xh2 = (const uint32_t*)Xh;
    const uint32_t* Xl2 = (const uint32_t*)Xl;
    const uint32_t* Wh2 = (const uint32_t*)Wh;
    const uint32_t* Wl2 = (const uint32_t*)Wl;

    for (int ocb = 0; ocb < 4; ocb++) {
        const int o0 = ocb * OC;
        __syncthreads();
        for (int idx = tid; idx < OC * 64; idx += 512) {
            int o = idx >> 6, c = idx & 63;
            float v = wqkv[(o0 + o) * 64 + c];
            __nv_bfloat16 h = __float2bfloat16(v);
            Wh[o * XS + c] = h;
            Wl[o * XS + c] = __float2bfloat16(v - __bfloat162float(h));
        }
        for (int idx = tid; idx < OC * 9; idx += 512)
            sdw[idx] = wdw[(o0 + idx / 9) * 9 + idx % 9];
        __syncthreads();

        // MMA: 42 units = 21 m-tiles x 2 n-halves (3 n-tiles each), 16 warps.
        for (int u = warp; u < 42; u += 16) {
            const int mt = u >> 1, nh = u & 1;
            const int m0 = mt * 16, n0 = nh * 3;
            float acc[3][4];
            #pragma unroll
            for (int n = 0; n < 3; n++)
                acc[n][0] = acc[n][1] = acc[n][2] = acc[n][3] = 0.f;

            #pragma unroll
            for (int kb = 0; kb < 4; kb++) {
                const int kw = kb * 8;
                const int rA = (m0 + gid) * 36 + kw + tig;
                uint32_t ah0 = Xh2[rA];
                uint32_t ah1 = Xh2[rA + 288];
                uint32_t ah2 = Xh2[rA + 4];
                uint32_t ah3 = Xh2[rA + 292];
                uint32_t al0 = Xl2[rA];
                uint32_t al1 = Xl2[rA + 288];
                uint32_t al2 = Xl2[rA + 4];
                uint32_t al3 = Xl2[rA + 292];
                #pragma unroll
                for (int n = 0; n < 3; n++) {
                    const int rB = ((n0 + n) * 8 + gid) * 36 + kw + tig;
                    uint32_t bh0 = Wh2[rB], bh1 = Wh2[rB + 4];
                    uint32_t bl0 = Wl2[rB], bl1 = Wl2[rB + 4];
                    mma_bf16(acc[n], ah0, ah1, ah2, ah3, bh0, bh1);
                    mma_bf16(acc[n], al0, al1, al2, al3, bh0, bh1);
                    mma_bf16(acc[n], ah0, ah1, ah2, ah3, bl0, bl1);
                }
            }
            #pragma unroll
            for (int n = 0; n < 3; n++) {
                const int oo = (n0 + n) * 8 + 2 * tig;
                sq[oo * SQS + m0 + gid]           = acc[n][0];
                sq[(oo + 1) * SQS + m0 + gid]     = acc[n][1];
                sq[oo * SQS + m0 + gid + 8]       = acc[n][2];
                sq[(oo + 1) * SQS + m0 + gid + 8] = acc[n][3];
            }
        }
        __syncthreads();

        // depthwise 3x3 on interior; write q,k split planes / V f32
        for (int idx = tid; idx < OC * 256; idx += 512) {
            int o = idx >> 8, p = idx & 255;
            int iy = p >> 4, ix = p & 15;
            const float* q = &sq[o * SQS + iy * 18 + ix];
            const float* d = &sdw[o * 9];
            float acc = d[0]*q[0]  + d[1]*q[1]  + d[2]*q[2]
                      + d[3]*q[18] + d[4]*q[19] + d[5]*q[20]
                      + d[6]*q[36] + d[7]*q[37] + d[8]*q[38];
            int gy = ty * 16 + iy, gx = tx * 16 + ix;
            int og = o0 + o;
            if (og < 128) {
                __nv_bfloat16 hh = __float2bfloat16(acc);
                __nv_bfloat16 ll = __float2bfloat16(acc - __bfloat162float(hh));
                size_t pi = ((size_t)b * 128 + og) * HW + gy * 256 + gx;
                g_qkh[pi] = hh;
                g_qkl[pi] = ll;
            } else {
                g_v[((size_t)b * 64 + (og - 128)) * HW + gy * 256 + gx] = acc;
            }
        }
    }
}

// ===========================================================================
// K2: sim partials via bf16-split MMA. Block=(b,h,r,half), 256 thr, 8 warps.
// smem: 2 buffers x {Ah,Al,Bh,Bl}[64 tok][72 kl] bf16; cp.async 16B loads.
// Warp w owns n-tile w (8 cols of j) x 4 m-tiles; acc fp32 across 16 chunks.
// ===========================================================================
#define K2MAT 2304   // 32-bit words per matrix (64*72/2)
#define K2BUF 9216   // words per buffer (4 matrices)

__global__ __launch_bounds__(256) void k2_sim()
{
    uint32_t* S = (uint32_t*)dsm;
    const int blk = blockIdx.x;
    const int half = blk & 1, r = (blk >> 1) & 3, h = (blk >> 3) & 7, b = blk >> 6;
    const int tid = threadIdx.x, warp = tid >> 5, lane = tid & 31;
    const int gid = lane >> 2, tig = lane & 3;
    const int yoff = h * 4 + r;

    const __nv_bfloat16* qh = g_qkh + (size_t)b * 128 * HW;
    const __nv_bfloat16* kh = qh + (size_t)64 * HW;
    const __nv_bfloat16* ql = g_qkl + (size_t)b * 128 * HW;
    const __nv_bfloat16* kl_ = ql + (size_t)64 * HW;

    // load slots: per plane, 2 groups of 8 bf16 per thread
    int off0[2], sb[2];
    #pragma unroll
    for (int s = 0; s < 2; s++) {
        int g = tid + s * 256;
        int t = g >> 3, k8 = g & 7;
        int chp = k8 >> 2, col8 = (k8 & 3) * 8;
        off0[s] = chp * HW + ((t >> 3) * 32 + yoff) * 256 + (t & 7) * 32 + col8;
        sb[s] = t * 144 + k8 * 16;   // byte offset within one matrix
    }
    const uint32_t shb = (uint32_t)__cvta_generic_to_shared(S);

    const int kc0 = half * 16;

    // prologue: chunk kc0 -> buffer 0
    {
        size_t co = (size_t)kc0 * 2 * HW;
        #pragma unroll
        for (int s = 0; s < 2; s++) {
            cp16(shb + 0 * K2MAT * 4 + sb[s], qh  + co + off0[s]);
            cp16(shb + 1 * K2MAT * 4 + sb[s], ql  + co + off0[s]);
            cp16(shb + 2 * K2MAT * 4 + sb[s], kh  + co + off0[s]);
            cp16(shb + 3 * K2MAT * 4 + sb[s], kl_ + co + off0[s]);
        }
        cp_commit();
    }

    float acc[4][4];
    #pragma unroll
    for (int mt = 0; mt < 4; mt++)
        acc[mt][0] = acc[mt][1] = acc[mt][2] = acc[mt][3] = 0.f;

    int buf = 0;
    for (int i = 0; i < 16; i++) {
        cp_wait0();
        __syncthreads();  // buf data visible; all warps done with buf^1
        if (i < 15) {
            size_t co = (size_t)(kc0 + i + 1) * 2 * HW;
            uint32_t bb = shb + (buf ^ 1) * (K2BUF * 4);
            #pragma unroll
            for (int s = 0; s < 2; s++) {
                cp16(bb + 0 * K2MAT * 4 + sb[s], qh  + co + off0[s]);
                cp16(bb + 1 * K2MAT * 4 + sb[s], ql  + co + off0[s]);
                cp16(bb + 2 * K2MAT * 4 + sb[s], kh  + co + off0[s]);
                cp16(bb + 3 * K2MAT * 4 + sb[s], kl_ + co + off0[s]);
            }
            cp_commit();
        }
        const uint32_t* Sw = S + buf * K2BUF;
        #pragma unroll
        for (int kb = 0; kb < 4; kb++) {
            const int rB = (warp * 8 + gid) * 36 + kb * 8 + tig;
            uint32_t bh0 = Sw[2 * K2MAT + rB], bh1 = Sw[2 * K2MAT + rB + 4];
            uint32_t bl0 = Sw[3 * K2MAT + rB], bl1 = Sw[3 * K2MAT + rB + 4];
            #pragma unroll
            for (int mt = 0; mt < 4; mt++) {
                const int rA = (mt * 16 + gid) * 36 + kb * 8 + tig;
                uint32_t ah0 = Sw[rA],          ah1 = Sw[rA + 288];
                uint32_t ah2 = Sw[rA + 4],      ah3 = Sw[rA + 292];
                uint32_t al0 = Sw[K2MAT + rA],     al1 = Sw[K2MAT + rA + 288];
                uint32_t al2 = Sw[K2MAT + rA + 4], al3 = Sw[K2MAT + rA + 292];
                mma_bf16(acc[mt], ah0, ah1, ah2, ah3, bh0, bh1);
                mma_bf16(acc[mt], al0, al1, al2, al3, bh0, bh1);
                mma_bf16(acc[mt], ah0, ah1, ah2, ah3, bl0, bl1);
            }
        }
        buf ^= 1;
    }

    float* so = g_sim + (size_t)blk * 4096;
    #pragma unroll
    for (int mt = 0; mt < 4; mt++) {
        const int rrow = mt * 16 + gid, ccol = warp * 8 + 2 * tig;
        so[rrow * 64 + ccol]           = acc[mt][0];
        so[rrow * 64 + ccol + 1]       = acc[mt][1];
        so[(rrow + 8) * 64 + ccol]     = acc[mt][2];
        so[(rrow + 8) * 64 + ccol + 1] = acc[mt][3];
    }
}

// ===========================================================================
// K3: softmax over j(64) of scale * (sum of 8 partials) + pos_emb
// ===========================================================================
__global__ __launch_bounds__(128) void k3_softmax(const float* __restrict__ pos)
{
    const float SCALE = 0.011048543456039806f;  // 8192^-0.5
    int row = blockIdx.x * 4 + (threadIdx.x >> 5);
    int lane = threadIdx.x & 31;
    int bh = row >> 6, i = row & 63;
    const float* s0 = g_sim + (size_t)bh * 8 * 4096 + i * 64;
    const float* pe = pos + (bh & 7) * 4096 + i * 64;
    float acc1 = 0.f, acc2 = 0.f;
    #pragma unroll
    for (int p = 0; p < 8; p++) {
        acc1 += s0[p * 4096 + lane];
        acc2 += s0[p * 4096 + lane + 32];
    }
    float v1 = SCALE * acc1 + pe[lane];
    float v2 = SCALE * acc2 + pe[lane + 32];
    float m = fmaxf(v1, v2);
    #pragma unroll
    for (int o = 16; o; o >>= 1) m = fmaxf(m, __shfl_xor_sync(0xffffffffu, m, o));
    float e1 = __expf(v1 - m), e2 = __expf(v2 - m);
    float s = e1 + e2;
    #pragma unroll
    for (int o = 16; o; o >>= 1) s += __shfl_xor_sync(0xffffffffu, s, o);
    float inv = 1.f / s;
    g_attn[(size_t)row * 64 + lane]      = e1 * inv;
    g_attn[(size_t)row * 64 + lane + 32] = e2 * inv;
}

// ===========================================================================
// K4: out = attn @ V (scalar, R6 register-prefetch variant). Block=(b,h,r,cg).
// ===========================================================================
__global__ __launch_bounds__(256) void k4_av()
{
    __shared__ float At[64 * 68];  // [j][t]
    __shared__ float Vs[64 * 68];  // [j][cc]
    const int blk = blockIdx.x;
    const int cg = blk & 1, r = (blk >> 1) & 3, h = (blk >> 3) & 7, b = blk >> 6;
    const int tid = threadIdx.x, ti = tid >> 4, tj = tid & 15;
    const int yoff = h * 4 + r;

    const float* ap = g_attn + (size_t)(b * 8 + h) * 4096;
    for (int idx = tid; idx < 4096; idx += 256) {
        int t = idx >> 6, j = idx & 63;
        At[j * 68 + t] = ap[t * 64 + j];
    }
    const float* vbase = g_v + (size_t)b * 64 * HW;
    float* ob = g_av + (size_t)b * 64 * HW;
    const float4* At4 = (const float4*)At;
    const float4* Vs4 = (const float4*)Vs;

    int jj[16], kk_[16];
    size_t goff[16];
    #pragma unroll
    for (int p = 0; p < 16; p++) {
        int idx = tid + p * 256;
        int j = idx >> 6, kl = idx & 63;
        int chp = kl >> 5, col = kl & 31;
        int y = (j >> 3) * 32 + yoff, xx = (j & 7) * 32 + col;
        jj[p] = j; kk_[p] = kl;
        goff[p] = (size_t)chp * HW + y * 256 + xx;
    }

    const int cp0 = cg * 16;
    float pv[16];
    #pragma unroll
    for (int p = 0; p < 16; p++)
        pv[p] = vbase[(size_t)cp0 * 2 * HW + goff[p]];

    for (int cp = cp0; cp < cp0 + 16; cp++) {
        __syncthreads();
        #pragma unroll
        for (int p = 0; p < 16; p++)
            Vs[jj[p] * 68 + kk_[p]] = pv[p];
        __syncthreads();
        if (cp + 1 < cp0 + 16) {
            #pragma unroll
            for (int p = 0; p < 16; p++)
                pv[p] = vbase[(size_t)(cp + 1) * 2 * HW + goff[p]];
        }
        float c00=0,c01=0,c02=0,c03=0, c10=0,c11=0,c12=0,c13=0;
        float c20=0,c21=0,c22=0,c23=0, c30=0,c31=0,c32=0,c33=0;
        #pragma unroll 8
        for (int kk = 0; kk < 64; kk++) {
            float4 av = At4[kk * 17 + ti];
            float4 vv = Vs4[kk * 17 + tj];
            c00 += av.x*vv.x; c01 += av.x*vv.y; c02 += av.x*vv.z; c03 += av.x*vv.w;
            c10 += av.y*vv.x; c11 += av.y*vv.y; c12 += av.y*vv.z; c13 += av.y*vv.w;
            c20 += av.z*vv.x; c21 += av.z*vv.y; c22 += av.z*vv.z; c23 += av.z*vv.w;
            c30 += av.w*vv.x; c31 += av.w*vv.y; c32 += av.w*vv.z; c33 += av.w*vv.w;
        }
        int cc0 = tj * 4, chp = cc0 >> 5, col0 = cc0 & 31;
        size_t cbase = (size_t)(cp * 2 + chp) * HW;
        float4 rows[4] = { make_float4(c00,c01,c02,c03), make_float4(c10,c11,c12,c13),
                           make_float4(c20,c21,c22,c23), make_float4(c30,c31,c32,c33) };
        #pragma unroll
        for (int ii = 0; ii < 4; ii++) {
            int t = ti * 4 + ii;
            int y = (t >> 3) * 32 + yoff;
            int xx = (t & 7) * 32 + col0;
            *(float4*)&ob[cbase + y * 256 + xx] = rows[ii];
        }
    }
}

// ===========================================================================
// K5: 1x1 projection + bias. Block = 128 positions; 8-out x 4-pos tiles.
// ===========================================================================
__global__ __launch_bounds__(256) void k5_proj(
    const float* __restrict__ wp, const float* __restrict__ bp,
    float* __restrict__ out)
{
    float* Ws = dsm;             // [64 c][68]
    float* Xs = Ws + 64 * 68;    // [64 c][132]
    const int blk = blockIdx.x;  // 8192 = 16 b * 256 y * 2 xh
    const int b = blk >> 9;
    const int rem = blk & 511;
    const int y = rem >> 1, x0 = (rem & 1) << 7;
    const int tid = threadIdx.x, to = tid >> 5, tp = tid & 31;

    const float* ib = g_av + (size_t)b * 64 * HW + y * 256 + x0;
    for (int idx = tid; idx < 4096; idx += 256) {
        int o = idx >> 6, c = idx & 63;
        Ws[c * 68 + o] = wp[o * 64 + c];
    }
    #pragma unroll
    for (int p = 0; p < 32; p++) {
        int idx = tid + p * 256;
        int c = idx >> 7, px = idx & 127;
        Xs[c * 132 + px] = ib[(size_t)c * HW + px];
    }
    __syncthreads();

    const float4* Ws4 = (const float4*)Ws;
    const float4* Xs4 = (const float4*)Xs;
    float a0x=0,a0y=0,a0z=0,a0w=0, a1x=0,a1y=0,a1z=0,a1w=0;
    float a2x=0,a2y=0,a2z=0,a2w=0, a3x=0,a3y=0,a3z=0,a3w=0;
    float a4x=0,a4y=0,a4z=0,a4w=0, a5x=0,a5y=0,a5z=0,a5w=0;
    float a6x=0,a6y=0,a6z=0,a6w=0, a7x=0,a7y=0,a7z=0,a7w=0;
    #pragma unroll 8
    for (int c = 0; c < 64; c++) {
        float4 w0 = Ws4[c * 17 + to * 2];
        float4 w1 = Ws4[c * 17 + to * 2 + 1];
        float4 xv = Xs4[c * 33 + tp];
        a0x += w0.x*xv.x; a0y += w0.x*xv.y; a0z += w0.x*xv.z; a0w += w0.x*xv.w;
        a1x += w0.y*xv.x; a1y += w0.y*xv.y; a1z += w0.y*xv.z; a1w += w0.y*xv.w;
        a2x += w0.z*xv.x; a2y += w0.z*xv.y; a2z += w0.z*xv.z; a2w += w0.z*xv.w;
        a3x += w0.w*xv.x; a3y += w0.w*xv.y; a3z += w0.w*xv.z; a3w += w0.w*xv.w;
        a4x += w1.x*xv.x; a4y += w1.x*xv.y; a4z += w1.x*xv.z; a4w += w1.x*xv.w;
        a5x += w1.y*xv.x; a5y += w1.y*xv.y; a5z += w1.y*xv.z; a5w += w1.y*xv.w;
        a6x += w1.z*xv.x; a6y += w1.z*xv.y; a6z += w1.z*xv.z; a6w += w1.z*xv.w;
        a7x += w1.w*xv.x; a7y += w1.w*xv.y; a7z += w1.w*xv.z; a7w += w1.w*xv.w;
    }
    float* op = out + (size_t)b * 64 * HW + y * 256 + x0 + tp * 4;
    const int ob8 = to * 8;
    float4 res[8] = { make_float4(a0x,a0y,a0z,a0w), make_float4(a1x,a1y,a1z,a1w),
                      make_float4(a2x,a2y,a2z,a2w), make_float4(a3x,a3y,a3z,a3w),
                      make_float4(a4x,a4y,a4z,a4w), make_float4(a5x,a5y,a5z,a5w),
                      make_float4(a6x,a6y,a6z,a6w), make_float4(a7x,a7y,a7z,a7w) };
    #pragma unroll
    for (int rr = 0; rr < 8; rr++) {
        float bb = bp[ob8 + rr];
        float4 v = res[rr];
        v.x += bb; v.y += bb; v.z += bb; v.w += bb;
        *(float4*)&op[(size_t)(ob8 + rr) * HW] = v;
    }
}

// Dummy kernels: shift the ncu capture window (-s 5 -c 1 with profiled stream
// starting at app launch #4) so the captured launch lands on k1_qkv_dw.
__global__ void kdummy() {
    if (threadIdx.x == 0) g_dummy[blockIdx.x] = 1.0f;
}

// ===========================================================================
extern "C" void kernel_launch(void* const* d_in, const int* in_sizes, int n_in,
                              void* d_out, int out_size)
{
    const float* x     = (const float*)d_in[0];
    const float* wqkv  = (const float*)d_in[1];
    const float* wdw   = (const float*)d_in[2];
    const float* wproj = (const float*)d_in[3];
    const float* bproj = (const float*)d_in[4];
    const float* pos   = (const float*)d_in[5];
    float* out = (float*)d_out;

    const int smem1 = 2 * (336 * XS * 2) + OC * SQS * 4
                    + 2 * (OC * XS * 2) + OC * 9 * 4;   // 176,832 B
    const int smem2 = 2 * K2BUF * 4;                     // 73,728 B
    const int smem5 = (64 * 68 + 64 * 132) * 4;          // 51,200 B
    cudaFuncSetAttribute(k1_qkv_dw, cudaFuncAttributeMaxDynamicSharedMemorySize, smem1);
    cudaFuncSetAttribute(k2_sim,    cudaFuncAttributeMaxDynamicSharedMemorySize, smem2);
    cudaFuncSetAttribute(k5_proj,   cudaFuncAttributeMaxDynamicSharedMemorySize, smem5);

    k1_qkv_dw<<<dim3(16, 16, 16), 512, smem1>>>(x, wqkv, wdw);
    k2_sim<<<1024, 256, smem2>>>();
    k3_softmax<<<2048, 128>>>(pos);
    k4_av<<<1024, 256>>>();
    k5_proj<<<8192, 256, smem5>>>(wproj, bproj, out);
    kdummy<<<1, 32>>>();
    kdummy<<<1, 32>>>();
    kdummy<<<1, 32>>>();
}

// round 13
// speedup vs baseline: 1.5261x; 1.2529x over previous
#include <cuda_runtime.h>
#include <cuda_bf16.h>
#include <cstdint>

// ---------------------------------------------------------------------------
// NonLocalMSA fp32, round 13: K1 split into K1a (pure 1x1 bf16-split MMA GEMM,
// no halo, 2 blocks/SM) + K1b (memory-bound depthwise 3x3, coalesced row
// tiles). K2 MMA / K3 / K4 scalar / K5 unchanged from R12 best.
// ---------------------------------------------------------------------------

#define HW 65536  // 256*256

__device__ float g_qkv[16ull * 192 * 65536];          // 805 MB: 1x1 output (f32)
__device__ __nv_bfloat16 g_qkh[16ull * 128 * 65536];  // 268 MB: q/k hi planes
__device__ __nv_bfloat16 g_qkl[16ull * 128 * 65536];  // 268 MB: lo residual
__device__ float g_v  [16ull *  64 * 65536];          // 268 MB: V (f32)
__device__ float g_av [16ull *  64 * 65536];          // 268 MB
__device__ float g_sim[1024ull * 64 * 64];            // 16 MB
__device__ float g_attn[128ull * 64 * 64];            // 2 MB
__device__ float g_dummy[32];

extern __shared__ float dsm[];

__device__ __forceinline__ void mma_bf16(float* c,
    uint32_t a0, uint32_t a1, uint32_t a2, uint32_t a3,
    uint32_t b0, uint32_t b1)
{
    asm volatile(
        "mma.sync.aligned.m16n8k16.row.col.f32.bf16.bf16.f32 "
        "{%0,%1,%2,%3}, {%4,%5,%6,%7}, {%8,%9}, {%0,%1,%2,%3};"
        : "+f"(c[0]), "+f"(c[1]), "+f"(c[2]), "+f"(c[3])
        : "r"(a0), "r"(a1), "r"(a2), "r"(a3), "r"(b0), "r"(b1));
}

__device__ __forceinline__ void cp16(uint32_t saddr, const void* gptr) {
    asm volatile("cp.async.cg.shared.global [%0], [%1], 16;" :: "r"(saddr), "l"(gptr));
}
__device__ __forceinline__ void cp_commit() {
    asm volatile("cp.async.commit_group;");
}
__device__ __forceinline__ void cp_wait0() {
    asm volatile("cp.async.wait_group 0;" ::: "memory");
}

// ===========================================================================
// K1a: qkv = x @ Wqkv^T via bf16-split MMA. Block = 256 linear positions.
// X smem [256 pos][72 ch] bf16 hi/lo (stride 36 words, R10-verified mapping);
// W in 2 chunks of 96 out-ch. Warp = m-tile (A frags reused over 12 n-tiles,
// in 2 groups of 6 to cap registers). Direct f32 stores to g_qkv.
// ===========================================================================
__global__ __launch_bounds__(512, 2) void k1a_qkv(
    const float* __restrict__ x, const float* __restrict__ wqkv)
{
    __nv_bfloat16* Xh = (__nv_bfloat16*)dsm;       // [256][72]
    __nv_bfloat16* Xl = Xh + 256 * 72;
    __nv_bfloat16* Wh = Xl + 256 * 72;             // [96][72]
    __nv_bfloat16* Wl = Wh + 96 * 72;

    const int b = blockIdx.z;
    const int pos0 = blockIdx.x << 8;
    const int tid = threadIdx.x, warp = tid >> 5, lane = tid & 31;
    const int gid = lane >> 2, tig = lane & 3;
    const float* xb = x + (size_t)b * 64 * HW;

    for (int idx = tid; idx < 64 * 256; idx += 512) {
        int c = idx >> 8, p = idx & 255;
        float v = xb[c * HW + pos0 + p];
        __nv_bfloat16 h = __float2bfloat16(v);
        Xh[p * 72 + c] = h;
        Xl[p * 72 + c] = __float2bfloat16(v - __bfloat162float(h));
    }

    const uint32_t* Xh2 = (const uint32_t*)Xh;
    const uint32_t* Xl2 = (const uint32_t*)Xl;
    const uint32_t* Wh2 = (const uint32_t*)Wh;
    const uint32_t* Wl2 = (const uint32_t*)Wl;

    for (int half = 0; half < 2; half++) {
        const int o0 = half * 96;
        __syncthreads();  // X ready (1st); prior mma done with W (2nd)
        for (int idx = tid; idx < 96 * 64; idx += 512) {
            int o = idx >> 6, c = idx & 63;
            float v = wqkv[(o0 + o) * 64 + c];
            __nv_bfloat16 h = __float2bfloat16(v);
            Wh[o * 72 + c] = h;
            Wl[o * 72 + c] = __float2bfloat16(v - __bfloat162float(h));
        }
        __syncthreads();

        #pragma unroll
        for (int g = 0; g < 2; g++) {
            float acc[6][4];
            #pragma unroll
            for (int n = 0; n < 6; n++)
                acc[n][0] = acc[n][1] = acc[n][2] = acc[n][3] = 0.f;

            #pragma unroll
            for (int kb = 0; kb < 4; kb++) {
                const int kw = kb * 8;
                const int rA = (warp * 16 + gid) * 36 + kw + tig;
                uint32_t ah0 = Xh2[rA],     ah1 = Xh2[rA + 288];
                uint32_t ah2 = Xh2[rA + 4], ah3 = Xh2[rA + 292];
                uint32_t al0 = Xl2[rA],     al1 = Xl2[rA + 288];
                uint32_t al2 = Xl2[rA + 4], al3 = Xl2[rA + 292];
                #pragma unroll
                for (int n = 0; n < 6; n++) {
                    const int nt = g * 6 + n;
                    const int rB = (nt * 8 + gid) * 36 + kw + tig;
                    uint32_t bh0 = Wh2[rB], bh1 = Wh2[rB + 4];
                    uint32_t bl0 = Wl2[rB], bl1 = Wl2[rB + 4];
                    mma_bf16(acc[n], ah0, ah1, ah2, ah3, bh0, bh1);
                    mma_bf16(acc[n], al0, al1, al2, al3, bh0, bh1);
                    mma_bf16(acc[n], ah0, ah1, ah2, ah3, bl0, bl1);
                }
            }
            #pragma unroll
            for (int n = 0; n < 6; n++) {
                const int ch = o0 + (g * 6 + n) * 8 + 2 * tig;
                const int pos = pos0 + warp * 16 + gid;
                float* p0 = g_qkv + ((size_t)b * 192 + ch) * HW;
                float* p1 = p0 + HW;
                p0[pos]     = acc[n][0];
                p1[pos]     = acc[n][1];
                p0[pos + 8] = acc[n][2];
                p1[pos + 8] = acc[n][3];
            }
        }
    }
}

// ===========================================================================
// K1b: depthwise 3x3 (f32, exact) + split-plane epilogue.
// Block = 8 image rows x 256 cols x 8 channels. smem row tiles, x-halo via
// zero-padded columns, y-halo via zero fill.
// ===========================================================================
__global__ __launch_bounds__(512, 2) void k1b_dw(const float* __restrict__ wdw)
{
    float* sx  = dsm;            // [8 ch][10 rows][260]
    float* sdw = sx + 8 * 10 * 260;  // [72]

    const int yt = blockIdx.x, ch0 = blockIdx.y * 8, b = blockIdx.z;
    const int tid = threadIdx.x;

    for (int idx = tid; idx < 8 * 10 * 256; idx += 512) {
        int ch = idx / 2560, rem = idx - ch * 2560;
        int row = rem >> 8, xx = rem & 255;
        int gy = yt * 8 - 1 + row;
        float v = 0.f;
        if ((unsigned)gy < 256u)
            v = g_qkv[((size_t)b * 192 + ch0 + ch) * HW + gy * 256 + xx];
        sx[(ch * 10 + row) * 260 + 1 + xx] = v;
    }
    if (tid < 80) {
        int ch = tid / 10, row = tid - ch * 10;
        sx[(ch * 10 + row) * 260]       = 0.f;
        sx[(ch * 10 + row) * 260 + 257] = 0.f;
    }
    if (tid < 72) sdw[tid] = wdw[ch0 * 9 + tid];
    __syncthreads();

    for (int idx = tid; idx < 8 * 8 * 256; idx += 512) {
        int ch = idx >> 11, rem = idx & 2047;
        int row = rem >> 8, xx = rem & 255;
        const float* sp = &sx[(ch * 10 + row) * 260 + xx];
        const float* d = &sdw[ch * 9];
        float acc = d[0]*sp[0]   + d[1]*sp[1]   + d[2]*sp[2]
                  + d[3]*sp[260] + d[4]*sp[261] + d[5]*sp[262]
                  + d[6]*sp[520] + d[7]*sp[521] + d[8]*sp[522];
        int gy = yt * 8 + row;
        int og = ch0 + ch;
        if (og < 128) {
            __nv_bfloat16 hh = __float2bfloat16(acc);
            __nv_bfloat16 ll = __float2bfloat16(acc - __bfloat162float(hh));
            size_t pi = ((size_t)b * 128 + og) * HW + gy * 256 + xx;
            g_qkh[pi] = hh;
            g_qkl[pi] = ll;
        } else {
            g_v[((size_t)b * 64 + (og - 128)) * HW + gy * 256 + xx] = acc;
        }
    }
}

// ===========================================================================
// K2: sim partials via bf16-split MMA (R12, unchanged).
// ===========================================================================
#define K2MAT 2304   // 32-bit words per matrix (64*72/2)
#define K2BUF 9216   // words per buffer (4 matrices)

__global__ __launch_bounds__(256) void k2_sim()
{
    uint32_t* S = (uint32_t*)dsm;
    const int blk = blockIdx.x;
    const int half = blk & 1, r = (blk >> 1) & 3, h = (blk >> 3) & 7, b = blk >> 6;
    const int tid = threadIdx.x, warp = tid >> 5, lane = tid & 31;
    const int gid = lane >> 2, tig = lane & 3;
    const int yoff = h * 4 + r;

    const __nv_bfloat16* qh = g_qkh + (size_t)b * 128 * HW;
    const __nv_bfloat16* kh = qh + (size_t)64 * HW;
    const __nv_bfloat16* ql = g_qkl + (size_t)b * 128 * HW;
    const __nv_bfloat16* kl_ = ql + (size_t)64 * HW;

    int off0[2], sb[2];
    #pragma unroll
    for (int s = 0; s < 2; s++) {
        int g = tid + s * 256;
        int t = g >> 3, k8 = g & 7;
        int chp = k8 >> 2, col8 = (k8 & 3) * 8;
        off0[s] = chp * HW + ((t >> 3) * 32 + yoff) * 256 + (t & 7) * 32 + col8;
        sb[s] = t * 144 + k8 * 16;
    }
    const uint32_t shb = (uint32_t)__cvta_generic_to_shared(S);

    const int kc0 = half * 16;
    {
        size_t co = (size_t)kc0 * 2 * HW;
        #pragma unroll
        for (int s = 0; s < 2; s++) {
            cp16(shb + 0 * K2MAT * 4 + sb[s], qh  + co + off0[s]);
            cp16(shb + 1 * K2MAT * 4 + sb[s], ql  + co + off0[s]);
            cp16(shb + 2 * K2MAT * 4 + sb[s], kh  + co + off0[s]);
            cp16(shb + 3 * K2MAT * 4 + sb[s], kl_ + co + off0[s]);
        }
        cp_commit();
    }

    float acc[4][4];
    #pragma unroll
    for (int mt = 0; mt < 4; mt++)
        acc[mt][0] = acc[mt][1] = acc[mt][2] = acc[mt][3] = 0.f;

    int buf = 0;
    for (int i = 0; i < 16; i++) {
        cp_wait0();
        __syncthreads();
        if (i < 15) {
            size_t co = (size_t)(kc0 + i + 1) * 2 * HW;
            uint32_t bb = shb + (buf ^ 1) * (K2BUF * 4);
            #pragma unroll
            for (int s = 0; s < 2; s++) {
                cp16(bb + 0 * K2MAT * 4 + sb[s], qh  + co + off0[s]);
                cp16(bb + 1 * K2MAT * 4 + sb[s], ql  + co + off0[s]);
                cp16(bb + 2 * K2MAT * 4 + sb[s], kh  + co + off0[s]);
                cp16(bb + 3 * K2MAT * 4 + sb[s], kl_ + co + off0[s]);
            }
            cp_commit();
        }
        const uint32_t* Sw = S + buf * K2BUF;
        #pragma unroll
        for (int kb = 0; kb < 4; kb++) {
            const int rB = (warp * 8 + gid) * 36 + kb * 8 + tig;
            uint32_t bh0 = Sw[2 * K2MAT + rB], bh1 = Sw[2 * K2MAT + rB + 4];
            uint32_t bl0 = Sw[3 * K2MAT + rB], bl1 = Sw[3 * K2MAT + rB + 4];
            #pragma unroll
            for (int mt = 0; mt < 4; mt++) {
                const int rA = (mt * 16 + gid) * 36 + kb * 8 + tig;
                uint32_t ah0 = Sw[rA],          ah1 = Sw[rA + 288];
                uint32_t ah2 = Sw[rA + 4],      ah3 = Sw[rA + 292];
                uint32_t al0 = Sw[K2MAT + rA],     al1 = Sw[K2MAT + rA + 288];
                uint32_t al2 = Sw[K2MAT + rA + 4], al3 = Sw[K2MAT + rA + 292];
                mma_bf16(acc[mt], ah0, ah1, ah2, ah3, bh0, bh1);
                mma_bf16(acc[mt], al0, al1, al2, al3, bh0, bh1);
                mma_bf16(acc[mt], ah0, ah1, ah2, ah3, bl0, bl1);
            }
        }
        buf ^= 1;
    }

    float* so = g_sim + (size_t)blk * 4096;
    #pragma unroll
    for (int mt = 0; mt < 4; mt++) {
        const int rrow = mt * 16 + gid, ccol = warp * 8 + 2 * tig;
        so[rrow * 64 + ccol]           = acc[mt][0];
        so[rrow * 64 + ccol + 1]       = acc[mt][1];
        so[(rrow + 8) * 64 + ccol]     = acc[mt][2];
        so[(rrow + 8) * 64 + ccol + 1] = acc[mt][3];
    }
}

// ===========================================================================
// K3: softmax over j(64) of scale * (sum of 8 partials) + pos_emb
// ===========================================================================
__global__ __launch_bounds__(128) void k3_softmax(const float* __restrict__ pos)
{
    const float SCALE = 0.011048543456039806f;  // 8192^-0.5
    int row = blockIdx.x * 4 + (threadIdx.x >> 5);
    int lane = threadIdx.x & 31;
    int bh = row >> 6, i = row & 63;
    const float* s0 = g_sim + (size_t)bh * 8 * 4096 + i * 64;
    const float* pe = pos + (bh & 7) * 4096 + i * 64;
    float acc1 = 0.f, acc2 = 0.f;
    #pragma unroll
    for (int p = 0; p < 8; p++) {
        acc1 += s0[p * 4096 + lane];
        acc2 += s0[p * 4096 + lane + 32];
    }
    float v1 = SCALE * acc1 + pe[lane];
    float v2 = SCALE * acc2 + pe[lane + 32];
    float m = fmaxf(v1, v2);
    #pragma unroll
    for (int o = 16; o; o >>= 1) m = fmaxf(m, __shfl_xor_sync(0xffffffffu, m, o));
    float e1 = __expf(v1 - m), e2 = __expf(v2 - m);
    float s = e1 + e2;
    #pragma unroll
    for (int o = 16; o; o >>= 1) s += __shfl_xor_sync(0xffffffffu, s, o);
    float inv = 1.f / s;
    g_attn[(size_t)row * 64 + lane]      = e1 * inv;
    g_attn[(size_t)row * 64 + lane + 32] = e2 * inv;
}

// ===========================================================================
// K4: out = attn @ V (scalar, measured-best variant). Block=(b,h,r,cg).
// ===========================================================================
__global__ __launch_bounds__(256) void k4_av()
{
    __shared__ float At[64 * 68];  // [j][t]
    __shared__ float Vs[64 * 68];  // [j][cc]
    const int blk = blockIdx.x;
    const int cg = blk & 1, r = (blk >> 1) & 3, h = (blk >> 3) & 7, b = blk >> 6;
    const int tid = threadIdx.x, ti = tid >> 4, tj = tid & 15;
    const int yoff = h * 4 + r;

    const float* ap = g_attn + (size_t)(b * 8 + h) * 4096;
    for (int idx = tid; idx < 4096; idx += 256) {
        int t = idx >> 6, j = idx & 63;
        At[j * 68 + t] = ap[t * 64 + j];
    }
    const float* vbase = g_v + (size_t)b * 64 * HW;
    float* ob = g_av + (size_t)b * 64 * HW;
    const float4* At4 = (const float4*)At;
    const float4* Vs4 = (const float4*)Vs;

    int jj[16], kk_[16];
    size_t goff[16];
    #pragma unroll
    for (int p = 0; p < 16; p++) {
        int idx = tid + p * 256;
        int j = idx >> 6, kl = idx & 63;
        int chp = kl >> 5, col = kl & 31;
        int y = (j >> 3) * 32 + yoff, xx = (j & 7) * 32 + col;
        jj[p] = j; kk_[p] = kl;
        goff[p] = (size_t)chp * HW + y * 256 + xx;
    }

    const int cp0 = cg * 16;
    float pv[16];
    #pragma unroll
    for (int p = 0; p < 16; p++)
        pv[p] = vbase[(size_t)cp0 * 2 * HW + goff[p]];

    for (int cp = cp0; cp < cp0 + 16; cp++) {
        __syncthreads();
        #pragma unroll
        for (int p = 0; p < 16; p++)
            Vs[jj[p] * 68 + kk_[p]] = pv[p];
        __syncthreads();
        if (cp + 1 < cp0 + 16) {
            #pragma unroll
            for (int p = 0; p < 16; p++)
                pv[p] = vbase[(size_t)(cp + 1) * 2 * HW + goff[p]];
        }
        float c00=0,c01=0,c02=0,c03=0, c10=0,c11=0,c12=0,c13=0;
        float c20=0,c21=0,c22=0,c23=0, c30=0,c31=0,c32=0,c33=0;
        #pragma unroll 8
        for (int kk = 0; kk < 64; kk++) {
            float4 av = At4[kk * 17 + ti];
            float4 vv = Vs4[kk * 17 + tj];
            c00 += av.x*vv.x; c01 += av.x*vv.y; c02 += av.x*vv.z; c03 += av.x*vv.w;
            c10 += av.y*vv.x; c11 += av.y*vv.y; c12 += av.y*vv.z; c13 += av.y*vv.w;
            c20 += av.z*vv.x; c21 += av.z*vv.y; c22 += av.z*vv.z; c23 += av.z*vv.w;
            c30 += av.w*vv.x; c31 += av.w*vv.y; c32 += av.w*vv.z; c33 += av.w*vv.w;
        }
        int cc0 = tj * 4, chp = cc0 >> 5, col0 = cc0 & 31;
        size_t cbase = (size_t)(cp * 2 + chp) * HW;
        float4 rows[4] = { make_float4(c00,c01,c02,c03), make_float4(c10,c11,c12,c13),
                           make_float4(c20,c21,c22,c23), make_float4(c30,c31,c32,c33) };
        #pragma unroll
        for (int ii = 0; ii < 4; ii++) {
            int t = ti * 4 + ii;
            int y = (t >> 3) * 32 + yoff;
            int xx = (t & 7) * 32 + col0;
            *(float4*)&ob[cbase + y * 256 + xx] = rows[ii];
        }
    }
}

// ===========================================================================
// K5: 1x1 projection + bias. Block = 128 positions; 8-out x 4-pos tiles.
// ===========================================================================
__global__ __launch_bounds__(256) void k5_proj(
    const float* __restrict__ wp, const float* __restrict__ bp,
    float* __restrict__ out)
{
    float* Ws = dsm;             // [64 c][68]
    float* Xs = Ws + 64 * 68;    // [64 c][132]
    const int blk = blockIdx.x;  // 8192 = 16 b * 256 y * 2 xh
    const int b = blk >> 9;
    const int rem = blk & 511;
    const int y = rem >> 1, x0 = (rem & 1) << 7;
    const int tid = threadIdx.x, to = tid >> 5, tp = tid & 31;

    const float* ib = g_av + (size_t)b * 64 * HW + y * 256 + x0;
    for (int idx = tid; idx < 4096; idx += 256) {
        int o = idx >> 6, c = idx & 63;
        Ws[c * 68 + o] = wp[o * 64 + c];
    }
    #pragma unroll
    for (int p = 0; p < 32; p++) {
        int idx = tid + p * 256;
        int c = idx >> 7, px = idx & 127;
        Xs[c * 132 + px] = ib[(size_t)c * HW + px];
    }
    __syncthreads();

    const float4* Ws4 = (const float4*)Ws;
    const float4* Xs4 = (const float4*)Xs;
    float a0x=0,a0y=0,a0z=0,a0w=0, a1x=0,a1y=0,a1z=0,a1w=0;
    float a2x=0,a2y=0,a2z=0,a2w=0, a3x=0,a3y=0,a3z=0,a3w=0;
    float a4x=0,a4y=0,a4z=0,a4w=0, a5x=0,a5y=0,a5z=0,a5w=0;
    float a6x=0,a6y=0,a6z=0,a6w=0, a7x=0,a7y=0,a7z=0,a7w=0;
    #pragma unroll 8
    for (int c = 0; c < 64; c++) {
        float4 w0 = Ws4[c * 17 + to * 2];
        float4 w1 = Ws4[c * 17 + to * 2 + 1];
        float4 xv = Xs4[c * 33 + tp];
        a0x += w0.x*xv.x; a0y += w0.x*xv.y; a0z += w0.x*xv.z; a0w += w0.x*xv.w;
        a1x += w0.y*xv.x; a1y += w0.y*xv.y; a1z += w0.y*xv.z; a1w += w0.y*xv.w;
        a2x += w0.z*xv.x; a2y += w0.z*xv.y; a2z += w0.z*xv.z; a2w += w0.z*xv.w;
        a3x += w0.w*xv.x; a3y += w0.w*xv.y; a3z += w0.w*xv.z; a3w += w0.w*xv.w;
        a4x += w1.x*xv.x; a4y += w1.x*xv.y; a4z += w1.x*xv.z; a4w += w1.x*xv.w;
        a5x += w1.y*xv.x; a5y += w1.y*xv.y; a5z += w1.y*xv.z; a5w += w1.y*xv.w;
        a6x += w1.z*xv.x; a6y += w1.z*xv.y; a6z += w1.z*xv.z; a6w += w1.z*xv.w;
        a7x += w1.w*xv.x; a7y += w1.w*xv.y; a7z += w1.w*xv.z; a7w += w1.w*xv.w;
    }
    float* op = out + (size_t)b * 64 * HW + y * 256 + x0 + tp * 4;
    const int ob8 = to * 8;
    float4 res[8] = { make_float4(a0x,a0y,a0z,a0w), make_float4(a1x,a1y,a1z,a1w),
                      make_float4(a2x,a2y,a2z,a2w), make_float4(a3x,a3y,a3z,a3w),
                      make_float4(a4x,a4y,a4z,a4w), make_float4(a5x,a5y,a5z,a5w),
                      make_float4(a6x,a6y,a6z,a6w), make_float4(a7x,a7y,a7z,a7w) };
    #pragma unroll
    for (int rr = 0; rr < 8; rr++) {
        float bb = bp[ob8 + rr];
        float4 v = res[rr];
        v.x += bb; v.y += bb; v.z += bb; v.w += bb;
        *(float4*)&op[(size_t)(ob8 + rr) * HW] = v;
    }
}

__global__ void kdummy() {
    if (threadIdx.x == 0) g_dummy[blockIdx.x] = 1.0f;
}

// ===========================================================================
extern "C" void kernel_launch(void* const* d_in, const int* in_sizes, int n_in,
                              void* d_out, int out_size)
{
    const float* x     = (const float*)d_in[0];
    const float* wqkv  = (const float*)d_in[1];
    const float* wdw   = (const float*)d_in[2];
    const float* wproj = (const float*)d_in[3];
    const float* bproj = (const float*)d_in[4];
    const float* pos   = (const float*)d_in[5];
    float* out = (float*)d_out;

    const int smem1a = (256 * 72 * 2 + 96 * 72 * 2) * 2;  // 101,376 B
    const int smem1b = (8 * 10 * 260 + 72) * 4;           // 83,488 B
    const int smem2  = 2 * K2BUF * 4;                     // 73,728 B
    const int smem5  = (64 * 68 + 64 * 132) * 4;          // 51,200 B
    cudaFuncSetAttribute(k1a_qkv, cudaFuncAttributeMaxDynamicSharedMemorySize, smem1a);
    cudaFuncSetAttribute(k1b_dw,  cudaFuncAttributeMaxDynamicSharedMemorySize, smem1b);
    cudaFuncSetAttribute(k2_sim,  cudaFuncAttributeMaxDynamicSharedMemorySize, smem2);
    cudaFuncSetAttribute(k5_proj, cudaFuncAttributeMaxDynamicSharedMemorySize, smem5);

    k1a_qkv<<<dim3(256, 1, 16), 512, smem1a>>>(x, wqkv);
    k1b_dw<<<dim3(32, 24, 16), 512, smem1b>>>(wdw);
    k2_sim<<<1024, 256, smem2>>>();
    k3_softmax<<<2048, 128>>>(pos);
    k4_av<<<1024, 256>>>();
    k5_proj<<<8192, 256, smem5>>>(wproj, bproj, out);
    kdummy<<<1, 32>>>();
    kdummy<<<1, 32>>>();
    kdummy<<<1, 32>>>();
    kdummy<<<1, 32>>>();
}

// round 14
// speedup vs baseline: 1.5544x; 1.0185x over previous
#include <cuda_runtime.h>
#include <cuda_bf16.h>
#include <cstdint>

// ---------------------------------------------------------------------------
// NonLocalMSA fp32, round 14: K5 converted to bf16-split MMA (clone of the
// verified K1a structure, N=64 + bias). K1a/K1b/K2/K3/K4 unchanged from R13.
// ---------------------------------------------------------------------------

#define HW 65536  // 256*256

__device__ float g_qkv[16ull * 192 * 65536];          // 805 MB: 1x1 output (f32)
__device__ __nv_bfloat16 g_qkh[16ull * 128 * 65536];  // 268 MB: q/k hi planes
__device__ __nv_bfloat16 g_qkl[16ull * 128 * 65536];  // 268 MB: lo residual
__device__ float g_v  [16ull *  64 * 65536];          // 268 MB: V (f32)
__device__ float g_av [16ull *  64 * 65536];          // 268 MB
__device__ float g_sim[1024ull * 64 * 64];            // 16 MB
__device__ float g_attn[128ull * 64 * 64];            // 2 MB
__device__ float g_dummy[32];

extern __shared__ float dsm[];

__device__ __forceinline__ void mma_bf16(float* c,
    uint32_t a0, uint32_t a1, uint32_t a2, uint32_t a3,
    uint32_t b0, uint32_t b1)
{
    asm volatile(
        "mma.sync.aligned.m16n8k16.row.col.f32.bf16.bf16.f32 "
        "{%0,%1,%2,%3}, {%4,%5,%6,%7}, {%8,%9}, {%0,%1,%2,%3};"
        : "+f"(c[0]), "+f"(c[1]), "+f"(c[2]), "+f"(c[3])
        : "r"(a0), "r"(a1), "r"(a2), "r"(a3), "r"(b0), "r"(b1));
}

__device__ __forceinline__ void cp16(uint32_t saddr, const void* gptr) {
    asm volatile("cp.async.cg.shared.global [%0], [%1], 16;" :: "r"(saddr), "l"(gptr));
}
__device__ __forceinline__ void cp_commit() {
    asm volatile("cp.async.commit_group;");
}
__device__ __forceinline__ void cp_wait0() {
    asm volatile("cp.async.wait_group 0;" ::: "memory");
}

// ===========================================================================
// K1a: qkv = x @ Wqkv^T via bf16-split MMA (R13, unchanged).
// ===========================================================================
__global__ __launch_bounds__(512, 2) void k1a_qkv(
    const float* __restrict__ x, const float* __restrict__ wqkv)
{
    __nv_bfloat16* Xh = (__nv_bfloat16*)dsm;       // [256][72]
    __nv_bfloat16* Xl = Xh + 256 * 72;
    __nv_bfloat16* Wh = Xl + 256 * 72;             // [96][72]
    __nv_bfloat16* Wl = Wh + 96 * 72;

    const int b = blockIdx.z;
    const int pos0 = blockIdx.x << 8;
    const int tid = threadIdx.x, warp = tid >> 5, lane = tid & 31;
    const int gid = lane >> 2, tig = lane & 3;
    const float* xb = x + (size_t)b * 64 * HW;

    for (int idx = tid; idx < 64 * 256; idx += 512) {
        int c = idx >> 8, p = idx & 255;
        float v = xb[c * HW + pos0 + p];
        __nv_bfloat16 h = __float2bfloat16(v);
        Xh[p * 72 + c] = h;
        Xl[p * 72 + c] = __float2bfloat16(v - __bfloat162float(h));
    }

    const uint32_t* Xh2 = (const uint32_t*)Xh;
    const uint32_t* Xl2 = (const uint32_t*)Xl;
    const uint32_t* Wh2 = (const uint32_t*)Wh;
    const uint32_t* Wl2 = (const uint32_t*)Wl;

    for (int half = 0; half < 2; half++) {
        const int o0 = half * 96;
        __syncthreads();
        for (int idx = tid; idx < 96 * 64; idx += 512) {
            int o = idx >> 6, c = idx & 63;
            float v = wqkv[(o0 + o) * 64 + c];
            __nv_bfloat16 h = __float2bfloat16(v);
            Wh[o * 72 + c] = h;
            Wl[o * 72 + c] = __float2bfloat16(v - __bfloat162float(h));
        }
        __syncthreads();

        #pragma unroll
        for (int g = 0; g < 2; g++) {
            float acc[6][4];
            #pragma unroll
            for (int n = 0; n < 6; n++)
                acc[n][0] = acc[n][1] = acc[n][2] = acc[n][3] = 0.f;

            #pragma unroll
            for (int kb = 0; kb < 4; kb++) {
                const int kw = kb * 8;
                const int rA = (warp * 16 + gid) * 36 + kw + tig;
                uint32_t ah0 = Xh2[rA],     ah1 = Xh2[rA + 288];
                uint32_t ah2 = Xh2[rA + 4], ah3 = Xh2[rA + 292];
                uint32_t al0 = Xl2[rA],     al1 = Xl2[rA + 288];
                uint32_t al2 = Xl2[rA + 4], al3 = Xl2[rA + 292];
                #pragma unroll
                for (int n = 0; n < 6; n++) {
                    const int nt = g * 6 + n;
                    const int rB = (nt * 8 + gid) * 36 + kw + tig;
                    uint32_t bh0 = Wh2[rB], bh1 = Wh2[rB + 4];
                    uint32_t bl0 = Wl2[rB], bl1 = Wl2[rB + 4];
                    mma_bf16(acc[n], ah0, ah1, ah2, ah3, bh0, bh1);
                    mma_bf16(acc[n], al0, al1, al2, al3, bh0, bh1);
                    mma_bf16(acc[n], ah0, ah1, ah2, ah3, bl0, bl1);
                }
            }
            #pragma unroll
            for (int n = 0; n < 6; n++) {
                const int ch = o0 + (g * 6 + n) * 8 + 2 * tig;
                const int pos = pos0 + warp * 16 + gid;
                float* p0 = g_qkv + ((size_t)b * 192 + ch) * HW;
                float* p1 = p0 + HW;
                p0[pos]     = acc[n][0];
                p1[pos]     = acc[n][1];
                p0[pos + 8] = acc[n][2];
                p1[pos + 8] = acc[n][3];
            }
        }
    }
}

// ===========================================================================
// K1b: depthwise 3x3 (f32, exact) + split-plane epilogue (R13, unchanged).
// ===========================================================================
__global__ __launch_bounds__(512, 2) void k1b_dw(const float* __restrict__ wdw)
{
    float* sx  = dsm;                // [8 ch][10 rows][260]
    float* sdw = sx + 8 * 10 * 260;  // [72]

    const int yt = blockIdx.x, ch0 = blockIdx.y * 8, b = blockIdx.z;
    const int tid = threadIdx.x;

    for (int idx = tid; idx < 8 * 10 * 256; idx += 512) {
        int ch = idx / 2560, rem = idx - ch * 2560;
        int row = rem >> 8, xx = rem & 255;
        int gy = yt * 8 - 1 + row;
        float v = 0.f;
        if ((unsigned)gy < 256u)
            v = g_qkv[((size_t)b * 192 + ch0 + ch) * HW + gy * 256 + xx];
        sx[(ch * 10 + row) * 260 + 1 + xx] = v;
    }
    if (tid < 80) {
        int ch = tid / 10, row = tid - ch * 10;
        sx[(ch * 10 + row) * 260]       = 0.f;
        sx[(ch * 10 + row) * 260 + 257] = 0.f;
    }
    if (tid < 72) sdw[tid] = wdw[ch0 * 9 + tid];
    __syncthreads();

    for (int idx = tid; idx < 8 * 8 * 256; idx += 512) {
        int ch = idx >> 11, rem = idx & 2047;
        int row = rem >> 8, xx = rem & 255;
        const float* sp = &sx[(ch * 10 + row) * 260 + xx];
        const float* d = &sdw[ch * 9];
        float acc = d[0]*sp[0]   + d[1]*sp[1]   + d[2]*sp[2]
                  + d[3]*sp[260] + d[4]*sp[261] + d[5]*sp[262]
                  + d[6]*sp[520] + d[7]*sp[521] + d[8]*sp[522];
        int gy = yt * 8 + row;
        int og = ch0 + ch;
        if (og < 128) {
            __nv_bfloat16 hh = __float2bfloat16(acc);
            __nv_bfloat16 ll = __float2bfloat16(acc - __bfloat162float(hh));
            size_t pi = ((size_t)b * 128 + og) * HW + gy * 256 + xx;
            g_qkh[pi] = hh;
            g_qkl[pi] = ll;
        } else {
            g_v[((size_t)b * 64 + (og - 128)) * HW + gy * 256 + xx] = acc;
        }
    }
}

// ===========================================================================
// K2: sim partials via bf16-split MMA (R12, unchanged).
// ===========================================================================
#define K2MAT 2304   // 32-bit words per matrix (64*72/2)
#define K2BUF 9216   // words per buffer (4 matrices)

__global__ __launch_bounds__(256) void k2_sim()
{
    uint32_t* S = (uint32_t*)dsm;
    const int blk = blockIdx.x;
    const int half = blk & 1, r = (blk >> 1) & 3, h = (blk >> 3) & 7, b = blk >> 6;
    const int tid = threadIdx.x, warp = tid >> 5, lane = tid & 31;
    const int gid = lane >> 2, tig = lane & 3;
    const int yoff = h * 4 + r;

    const __nv_bfloat16* qh = g_qkh + (size_t)b * 128 * HW;
    const __nv_bfloat16* kh = qh + (size_t)64 * HW;
    const __nv_bfloat16* ql = g_qkl + (size_t)b * 128 * HW;
    const __nv_bfloat16* kl_ = ql + (size_t)64 * HW;

    int off0[2], sb[2];
    #pragma unroll
    for (int s = 0; s < 2; s++) {
        int g = tid + s * 256;
        int t = g >> 3, k8 = g & 7;
        int chp = k8 >> 2, col8 = (k8 & 3) * 8;
        off0[s] = chp * HW + ((t >> 3) * 32 + yoff) * 256 + (t & 7) * 32 + col8;
        sb[s] = t * 144 + k8 * 16;
    }
    const uint32_t shb = (uint32_t)__cvta_generic_to_shared(S);

    const int kc0 = half * 16;
    {
        size_t co = (size_t)kc0 * 2 * HW;
        #pragma unroll
        for (int s = 0; s < 2; s++) {
            cp16(shb + 0 * K2MAT * 4 + sb[s], qh  + co + off0[s]);
            cp16(shb + 1 * K2MAT * 4 + sb[s], ql  + co + off0[s]);
            cp16(shb + 2 * K2MAT * 4 + sb[s], kh  + co + off0[s]);
            cp16(shb + 3 * K2MAT * 4 + sb[s], kl_ + co + off0[s]);
        }
        cp_commit();
    }

    float acc[4][4];
    #pragma unroll
    for (int mt = 0; mt < 4; mt++)
        acc[mt][0] = acc[mt][1] = acc[mt][2] = acc[mt][3] = 0.f;

    int buf = 0;
    for (int i = 0; i < 16; i++) {
        cp_wait0();
        __syncthreads();
        if (i < 15) {
            size_t co = (size_t)(kc0 + i + 1) * 2 * HW;
            uint32_t bb = shb + (buf ^ 1) * (K2BUF * 4);
            #pragma unroll
            for (int s = 0; s < 2; s++) {
                cp16(bb + 0 * K2MAT * 4 + sb[s], qh  + co + off0[s]);
                cp16(bb + 1 * K2MAT * 4 + sb[s], ql  + co + off0[s]);
                cp16(bb + 2 * K2MAT * 4 + sb[s], kh  + co + off0[s]);
                cp16(bb + 3 * K2MAT * 4 + sb[s], kl_ + co + off0[s]);
            }
            cp_commit();
        }
        const uint32_t* Sw = S + buf * K2BUF;
        #pragma unroll
        for (int kb = 0; kb < 4; kb++) {
            const int rB = (warp * 8 + gid) * 36 + kb * 8 + tig;
            uint32_t bh0 = Sw[2 * K2MAT + rB], bh1 = Sw[2 * K2MAT + rB + 4];
            uint32_t bl0 = Sw[3 * K2MAT + rB], bl1 = Sw[3 * K2MAT + rB + 4];
            #pragma unroll
            for (int mt = 0; mt < 4; mt++) {
                const int rA = (mt * 16 + gid) * 36 + kb * 8 + tig;
                uint32_t ah0 = Sw[rA],          ah1 = Sw[rA + 288];
                uint32_t ah2 = Sw[rA + 4],      ah3 = Sw[rA + 292];
                uint32_t al0 = Sw[K2MAT + rA],     al1 = Sw[K2MAT + rA + 288];
                uint32_t al2 = Sw[K2MAT + rA + 4], al3 = Sw[K2MAT + rA + 292];
                mma_bf16(acc[mt], ah0, ah1, ah2, ah3, bh0, bh1);
                mma_bf16(acc[mt], al0, al1, al2, al3, bh0, bh1);
                mma_bf16(acc[mt], ah0, ah1, ah2, ah3, bl0, bl1);
            }
        }
        buf ^= 1;
    }

    float* so = g_sim + (size_t)blk * 4096;
    #pragma unroll
    for (int mt = 0; mt < 4; mt++) {
        const int rrow = mt * 16 + gid, ccol = warp * 8 + 2 * tig;
        so[rrow * 64 + ccol]           = acc[mt][0];
        so[rrow * 64 + ccol + 1]       = acc[mt][1];
        so[(rrow + 8) * 64 + ccol]     = acc[mt][2];
        so[(rrow + 8) * 64 + ccol + 1] = acc[mt][3];
    }
}

// ===========================================================================
// K3: softmax over j(64) of scale * (sum of 8 partials) + pos_emb
// ===========================================================================
__global__ __launch_bounds__(128) void k3_softmax(const float* __restrict__ pos)
{
    const float SCALE = 0.011048543456039806f;  // 8192^-0.5
    int row = blockIdx.x * 4 + (threadIdx.x >> 5);
    int lane = threadIdx.x & 31;
    int bh = row >> 6, i = row & 63;
    const float* s0 = g_sim + (size_t)bh * 8 * 4096 + i * 64;
    const float* pe = pos + (bh & 7) * 4096 + i * 64;
    float acc1 = 0.f, acc2 = 0.f;
    #pragma unroll
    for (int p = 0; p < 8; p++) {
        acc1 += s0[p * 4096 + lane];
        acc2 += s0[p * 4096 + lane + 32];
    }
    float v1 = SCALE * acc1 + pe[lane];
    float v2 = SCALE * acc2 + pe[lane + 32];
    float m = fmaxf(v1, v2);
    #pragma unroll
    for (int o = 16; o; o >>= 1) m = fmaxf(m, __shfl_xor_sync(0xffffffffu, m, o));
    float e1 = __expf(v1 - m), e2 = __expf(v2 - m);
    float s = e1 + e2;
    #pragma unroll
    for (int o = 16; o; o >>= 1) s += __shfl_xor_sync(0xffffffffu, s, o);
    float inv = 1.f / s;
    g_attn[(size_t)row * 64 + lane]      = e1 * inv;
    g_attn[(size_t)row * 64 + lane + 32] = e2 * inv;
}

// ===========================================================================
// K4: out = attn @ V (scalar, measured-best variant). Block=(b,h,r,cg).
// ===========================================================================
__global__ __launch_bounds__(256) void k4_av()
{
    __shared__ float At[64 * 68];  // [j][t]
    __shared__ float Vs[64 * 68];  // [j][cc]
    const int blk = blockIdx.x;
    const int cg = blk & 1, r = (blk >> 1) & 3, h = (blk >> 3) & 7, b = blk >> 6;
    const int tid = threadIdx.x, ti = tid >> 4, tj = tid & 15;
    const int yoff = h * 4 + r;

    const float* ap = g_attn + (size_t)(b * 8 + h) * 4096;
    for (int idx = tid; idx < 4096; idx += 256) {
        int t = idx >> 6, j = idx & 63;
        At[j * 68 + t] = ap[t * 64 + j];
    }
    const float* vbase = g_v + (size_t)b * 64 * HW;
    float* ob = g_av + (size_t)b * 64 * HW;
    const float4* At4 = (const float4*)At;
    const float4* Vs4 = (const float4*)Vs;

    int jj[16], kk_[16];
    size_t goff[16];
    #pragma unroll
    for (int p = 0; p < 16; p++) {
        int idx = tid + p * 256;
        int j = idx >> 6, kl = idx & 63;
        int chp = kl >> 5, col = kl & 31;
        int y = (j >> 3) * 32 + yoff, xx = (j & 7) * 32 + col;
        jj[p] = j; kk_[p] = kl;
        goff[p] = (size_t)chp * HW + y * 256 + xx;
    }

    const int cp0 = cg * 16;
    float pv[16];
    #pragma unroll
    for (int p = 0; p < 16; p++)
        pv[p] = vbase[(size_t)cp0 * 2 * HW + goff[p]];

    for (int cp = cp0; cp < cp0 + 16; cp++) {
        __syncthreads();
        #pragma unroll
        for (int p = 0; p < 16; p++)
            Vs[jj[p] * 68 + kk_[p]] = pv[p];
        __syncthreads();
        if (cp + 1 < cp0 + 16) {
            #pragma unroll
            for (int p = 0; p < 16; p++)
                pv[p] = vbase[(size_t)(cp + 1) * 2 * HW + goff[p]];
        }
        float c00=0,c01=0,c02=0,c03=0, c10=0,c11=0,c12=0,c13=0;
        float c20=0,c21=0,c22=0,c23=0, c30=0,c31=0,c32=0,c33=0;
        #pragma unroll 8
        for (int kk = 0; kk < 64; kk++) {
            float4 av = At4[kk * 17 + ti];
            float4 vv = Vs4[kk * 17 + tj];
            c00 += av.x*vv.x; c01 += av.x*vv.y; c02 += av.x*vv.z; c03 += av.x*vv.w;
            c10 += av.y*vv.x; c11 += av.y*vv.y; c12 += av.y*vv.z; c13 += av.y*vv.w;
            c20 += av.z*vv.x; c21 += av.z*vv.y; c22 += av.z*vv.z; c23 += av.z*vv.w;
            c30 += av.w*vv.x; c31 += av.w*vv.y; c32 += av.w*vv.z; c33 += av.w*vv.w;
        }
        int cc0 = tj * 4, chp = cc0 >> 5, col0 = cc0 & 31;
        size_t cbase = (size_t)(cp * 2 + chp) * HW;
        float4 rows[4] = { make_float4(c00,c01,c02,c03), make_float4(c10,c11,c12,c13),
                           make_float4(c20,c21,c22,c23), make_float4(c30,c31,c32,c33) };
        #pragma unroll
        for (int ii = 0; ii < 4; ii++) {
            int t = ti * 4 + ii;
            int y = (t >> 3) * 32 + yoff;
            int xx = (t & 7) * 32 + col0;
            *(float4*)&ob[cbase + y * 256 + xx] = rows[ii];
        }
    }
}

// ===========================================================================
// K5: out = Wproj @ av + bias via bf16-split MMA (K1a clone, N=64).
// Block = 256 positions; X[256 p][72 c] split transposed, W[64 o][72 c] split.
// ===========================================================================
__global__ __launch_bounds__(512, 2) void k5_proj(
    const float* __restrict__ wp, const float* __restrict__ bp,
    float* __restrict__ out)
{
    __nv_bfloat16* Xh = (__nv_bfloat16*)dsm;       // [256][72]
    __nv_bfloat16* Xl = Xh + 256 * 72;
    __nv_bfloat16* Wh = Xl + 256 * 72;             // [64][72]
    __nv_bfloat16* Wl = Wh + 64 * 72;
    float* sbias      = (float*)(Wl + 64 * 72);    // [64]

    const int b = blockIdx.z;
    const int pos0 = blockIdx.x << 8;
    const int tid = threadIdx.x, warp = tid >> 5, lane = tid & 31;
    const int gid = lane >> 2, tig = lane & 3;
    const float* ab = g_av + (size_t)b * 64 * HW;

    for (int idx = tid; idx < 64 * 256; idx += 512) {
        int c = idx >> 8, p = idx & 255;
        float v = ab[c * HW + pos0 + p];
        __nv_bfloat16 h = __float2bfloat16(v);
        Xh[p * 72 + c] = h;
        Xl[p * 72 + c] = __float2bfloat16(v - __bfloat162float(h));
    }
    for (int idx = tid; idx < 64 * 64; idx += 512) {
        int o = idx >> 6, c = idx & 63;
        float v = wp[o * 64 + c];
        __nv_bfloat16 h = __float2bfloat16(v);
        Wh[o * 72 + c] = h;
        Wl[o * 72 + c] = __float2bfloat16(v - __bfloat162float(h));
    }
    if (tid < 64) sbias[tid] = bp[tid];
    __syncthreads();

    const uint32_t* Xh2 = (const uint32_t*)Xh;
    const uint32_t* Xl2 = (const uint32_t*)Xl;
    const uint32_t* Wh2 = (const uint32_t*)Wh;
    const uint32_t* Wl2 = (const uint32_t*)Wl;

    float* ob = out + (size_t)b * 64 * HW;

    #pragma unroll
    for (int g = 0; g < 2; g++) {
        float acc[4][4];
        #pragma unroll
        for (int n = 0; n < 4; n++)
            acc[n][0] = acc[n][1] = acc[n][2] = acc[n][3] = 0.f;

        #pragma unroll
        for (int kb = 0; kb < 4; kb++) {
            const int kw = kb * 8;
            const int rA = (warp * 16 + gid) * 36 + kw + tig;
            uint32_t ah0 = Xh2[rA],     ah1 = Xh2[rA + 288];
            uint32_t ah2 = Xh2[rA + 4], ah3 = Xh2[rA + 292];
            uint32_t al0 = Xl2[rA],     al1 = Xl2[rA + 288];
            uint32_t al2 = Xl2[rA + 4], al3 = Xl2[rA + 292];
            #pragma unroll
            for (int n = 0; n < 4; n++) {
                const int nt = g * 4 + n;
                const int rB = (nt * 8 + gid) * 36 + kw + tig;
                uint32_t bh0 = Wh2[rB], bh1 = Wh2[rB + 4];
                uint32_t bl0 = Wl2[rB], bl1 = Wl2[rB + 4];
                mma_bf16(acc[n], ah0, ah1, ah2, ah3, bh0, bh1);
                mma_bf16(acc[n], al0, al1, al2, al3, bh0, bh1);
                mma_bf16(acc[n], ah0, ah1, ah2, ah3, bl0, bl1);
            }
        }
        #pragma unroll
        for (int n = 0; n < 4; n++) {
            const int o = (g * 4 + n) * 8 + 2 * tig;
            const int pos = pos0 + warp * 16 + gid;
            float b0 = sbias[o], b1 = sbias[o + 1];
            ob[(size_t)o * HW + pos]           = acc[n][0] + b0;
            ob[(size_t)(o + 1) * HW + pos]     = acc[n][1] + b1;
            ob[(size_t)o * HW + pos + 8]       = acc[n][2] + b0;
            ob[(size_t)(o + 1) * HW + pos + 8] = acc[n][3] + b1;
        }
    }
}

__global__ void kdummy() {
    if (threadIdx.x == 0) g_dummy[blockIdx.x] = 1.0f;
}

// ===========================================================================
extern "C" void kernel_launch(void* const* d_in, const int* in_sizes, int n_in,
                              void* d_out, int out_size)
{
    const float* x     = (const float*)d_in[0];
    const float* wqkv  = (const float*)d_in[1];
    const float* wdw   = (const float*)d_in[2];
    const float* wproj = (const float*)d_in[3];
    const float* bproj = (const float*)d_in[4];
    const float* pos   = (const float*)d_in[5];
    float* out = (float*)d_out;

    const int smem1a = (256 * 72 * 2 + 96 * 72 * 2) * 2;         // 101,376 B
    const int smem1b = (8 * 10 * 260 + 72) * 4;                  // 83,488 B
    const int smem2  = 2 * K2BUF * 4;                            // 73,728 B
    const int smem5  = (256 * 72 + 64 * 72) * 2 * 2 + 64 * 4;    // 92,416 B
    cudaFuncSetAttribute(k1a_qkv, cudaFuncAttributeMaxDynamicSharedMemorySize, smem1a);
    cudaFuncSetAttribute(k1b_dw,  cudaFuncAttributeMaxDynamicSharedMemorySize, smem1b);
    cudaFuncSetAttribute(k2_sim,  cudaFuncAttributeMaxDynamicSharedMemorySize, smem2);
    cudaFuncSetAttribute(k5_proj, cudaFuncAttributeMaxDynamicSharedMemorySize, smem5);

    k1a_qkv<<<dim3(256, 1, 16), 512, smem1a>>>(x, wqkv);
    k1b_dw<<<dim3(32, 24, 16), 512, smem1b>>>(wdw);
    k2_sim<<<1024, 256, smem2>>>();
    k3_softmax<<<2048, 128>>>(pos);
    k4_av<<<1024, 256>>>();
    k5_proj<<<dim3(256, 1, 16), 512, smem5>>>(wproj, bproj, out);
    kdummy<<<1, 32>>>();
    kdummy<<<1, 32>>>();
    kdummy<<<1, 32>>>();
    kdummy<<<1, 32>>>();
}